// round 1
// baseline (speedup 1.0000x reference)
#include <cuda_runtime.h>
#include <math.h>

#define NB 512
#define NF 64
#define NK 64
#define LDW 65          // padded stride for W1 in smem

// upper-triangular 8x8 tile enumeration (36 tiles)
__device__ __constant__ unsigned char TI_ARR[36] = {
    0,0,0,0,0,0,0,0,
    1,1,1,1,1,1,1,
    2,2,2,2,2,2,
    3,3,3,3,3,
    4,4,4,4,
    5,5,5,
    6,6,
    7};
__device__ __constant__ unsigned char TJ_ARR[36] = {
    0,1,2,3,4,5,6,7,
    1,2,3,4,5,6,7,
    2,3,4,5,6,7,
    3,4,5,6,7,
    4,5,6,7,
    5,6,7,
    6,7,
    7};

__global__ void __launch_bounds__(256, 2)
afm_kernel(const float* __restrict__ x,
           const float* __restrict__ Ww,  const float* __restrict__ bw,
           const float* __restrict__ cross,
           const float* __restrict__ W1,  const float* __restrict__ b1,
           const float* __restrict__ w2,
           const float* __restrict__ Wd1, const float* __restrict__ bd1,
           const float* __restrict__ Wd2, const float* __restrict__ bd2,
           const float* __restrict__ Wd3, const float* __restrict__ bd3,
           const float* __restrict__ Wo,  const float* __restrict__ bo,
           float* __restrict__ out)
{
    // dynamic smem: u[64][64] then sv[64][64]
    extern __shared__ float dsm[];
    float* u  = dsm;            // u[i*64+k]
    float* sv = dsm + NF * NK;  // scores, then exp-weights

    __shared__ float w1s[NK * LDW];   // W1[l*65+k], padded
    __shared__ float xb[NF], b1s[NK], w2s[NK];
    __shared__ float redbuf[8];
    __shared__ float acc4[4][NK];
    __shared__ float tmpv[NK];
    __shared__ float d1s[32], d2s[24], d3s[16];
    __shared__ float m_sh, denom_sh;

    const int b   = blockIdx.x;
    const int tid = threadIdx.x;

    if (tid < NF) {
        xb[tid]  = x[b * NF + tid];
        b1s[tid] = b1[tid];
        w2s[tid] = w2[tid];
    }
    __syncthreads();

    for (int idx = tid; idx < NF * NK; idx += 256) {
        int r = idx >> 6, c = idx & 63;
        w1s[r * LDW + c] = W1[idx];
        u[idx]           = xb[r] * cross[idx];
    }
    __syncthreads();

    // ---------------- Pass 1: attention scores per pair tile ----------------
    const int slot = tid >> 6;      // 0..3  (4 concurrent tiles)
    const int t    = tid & 63;
    const int pi   = t >> 3;        // i within tile (0..7)
    const int lg   = t & 7;         // l-group (0..7), 8 l's each

    for (int tile = slot; tile < 36; tile += 4) {
        const int ti = TI_ARR[tile], tj = TJ_ARR[tile];
        const int i  = ti * 8 + pi;
        const float* ui = u + i * NK;
        const float* uj = u + (tj * 8) * NK;
        const float* wl = w1s + (lg * 8) * LDW;

        float acc[8][8];
        #pragma unroll
        for (int a = 0; a < 8; a++)
            #pragma unroll
            for (int c = 0; c < 8; c++) acc[a][c] = 0.f;

        for (int k = 0; k < NK; k++) {
            const float uik = ui[k];
            float tk[8];
            #pragma unroll
            for (int pj = 0; pj < 8; pj++) tk[pj] = uik * uj[pj * NK + k];
            #pragma unroll
            for (int q = 0; q < 8; q++) {
                const float w = wl[q * LDW + k];
                #pragma unroll
                for (int pj = 0; pj < 8; pj++)
                    acc[pj][q] = fmaf(tk[pj], w, acc[pj][q]);
            }
        }

        // relu(h)+bias, dot with w2 -> per-(i,j) partial over this l-group
        float sp[8];
        #pragma unroll
        for (int pj = 0; pj < 8; pj++) {
            float v = 0.f;
            #pragma unroll
            for (int q = 0; q < 8; q++) {
                float h = fmaxf(acc[pj][q] + b1s[lg * 8 + q], 0.f);
                v = fmaf(h, w2s[lg * 8 + q], v);
            }
            sp[pj] = v;
        }
        // reduce over the 8 l-groups (consecutive lanes)
        #pragma unroll
        for (int d = 1; d < 8; d <<= 1)
            #pragma unroll
            for (int pj = 0; pj < 8; pj++)
                sp[pj] += __shfl_xor_sync(0xffffffffu, sp[pj], d);

        if (lg == 0) {
            #pragma unroll
            for (int pj = 0; pj < 8; pj++)
                sv[i * NF + tj * 8 + pj] = sp[pj];
        }
    }
    __syncthreads();

    // ---------------- Pass 2: masked softmax ----------------
    float lm = -3.4e38f;
    for (int idx = tid; idx < NF * NF; idx += 256) {
        int i = idx >> 6, j = idx & 63;
        bool valid = (j >= i) && (xb[i] != 0.f) && (xb[j] != 0.f);
        if (valid) lm = fmaxf(lm, sv[idx]);
    }
    #pragma unroll
    for (int d = 16; d; d >>= 1) lm = fmaxf(lm, __shfl_xor_sync(~0u, lm, d));
    if ((tid & 31) == 0) redbuf[tid >> 5] = lm;
    __syncthreads();
    if (tid == 0) {
        float m = 0.f;   // max with the 0-logit seed term
        for (int w = 0; w < 8; w++) m = fmaxf(m, redbuf[w]);
        m_sh = m;
    }
    __syncthreads();
    const float m = m_sh;

    float le = 0.f;
    for (int idx = tid; idx < NF * NF; idx += 256) {
        int i = idx >> 6, j = idx & 63;
        bool valid = (j >= i) && (xb[i] != 0.f) && (xb[j] != 0.f);
        float e = valid ? expf(sv[idx] - m) : 0.f;
        sv[idx] = e;
        le += e;
    }
    #pragma unroll
    for (int d = 16; d; d >>= 1) le += __shfl_xor_sync(~0u, le, d);
    __syncthreads();                 // all sv writes done, redbuf reads done
    if ((tid & 31) == 0) redbuf[tid >> 5] = le;
    __syncthreads();
    if (tid == 0) {
        float tot = expf(-m);        // seed zeros(1) entry
        for (int w = 0; w < 8; w++) tot += redbuf[w];
        denom_sh = tot;
    }
    __syncthreads();

    // ---------------- Pass 3: tmp[k] = sum_ij e_ij * u_i[k]*u_j[k] / denom ----
    {
        const int k = tid & 63, g = tid >> 6;
        float a = 0.f;
        for (int i = g * 16; i < g * 16 + 16; i++) {
            const float* svi = sv + i * NF;
            float w = 0.f;
            #pragma unroll 4
            for (int j = 0; j < NF; j++)
                w = fmaf(svi[j], u[j * NK + k], w);
            a = fmaf(u[i * NK + k], w, a);
        }
        acc4[g][k] = a;
    }
    __syncthreads();
    if (tid < NK)
        tmpv[tid] = (acc4[0][tid] + acc4[1][tid] + acc4[2][tid] + acc4[3][tid])
                    / denom_sh;
    __syncthreads();

    // ---------------- Pass 4: deep MLP 64->32->21->16->1 + sigmoid ----------
    if (tid < 32) {
        float a = bd1[tid];
        const float* w = Wd1 + tid * 64;
        #pragma unroll 4
        for (int j = 0; j < 64; j++) a = fmaf(w[j], tmpv[j], a);
        d1s[tid] = fmaxf(a, 0.f);
    }
    __syncthreads();
    if (tid < 21) {
        float a = bd2[tid];
        const float* w = Wd2 + tid * 32;
        #pragma unroll 4
        for (int j = 0; j < 32; j++) a = fmaf(w[j], d1s[j], a);
        d2s[tid] = fmaxf(a, 0.f);
    }
    __syncthreads();
    if (tid < 16) {
        float a = bd3[tid];
        const float* w = Wd3 + tid * 21;
        for (int j = 0; j < 21; j++) a = fmaf(w[j], d2s[j], a);
        d3s[tid] = fmaxf(a, 0.f);
    }
    __syncthreads();
    if (tid == 0) {
        float o = bo[0];
        #pragma unroll
        for (int j = 0; j < 16; j++) o = fmaf(Wo[j], d3s[j], o);
        float lin = bw[0];
        #pragma unroll 4
        for (int f = 0; f < NF; f++) lin = fmaf(Ww[f], xb[f], lin);
        out[b] = 1.f / (1.f + expf(-(lin + o)));
    }
}

extern "C" void kernel_launch(void* const* d_in, const int* in_sizes, int n_in,
                              void* d_out, int out_size)
{
    const float* x     = (const float*)d_in[0];
    const float* Ww    = (const float*)d_in[1];
    const float* bw    = (const float*)d_in[2];
    const float* cross = (const float*)d_in[3];
    const float* W1    = (const float*)d_in[4];
    const float* b1    = (const float*)d_in[5];
    const float* w2    = (const float*)d_in[6];
    const float* Wd1   = (const float*)d_in[7];
    const float* bd1   = (const float*)d_in[8];
    const float* Wd2   = (const float*)d_in[9];
    const float* bd2   = (const float*)d_in[10];
    const float* Wd3   = (const float*)d_in[11];
    const float* bd3   = (const float*)d_in[12];
    const float* Wo    = (const float*)d_in[13];
    const float* bo    = (const float*)d_in[14];
    float* out = (float*)d_out;

    const size_t dyn_smem = (size_t)(NF * NK + NF * NF) * sizeof(float); // 32 KB
    // total (static ~19KB + dynamic 32KB) > 48KB default: opt in. Idempotent,
    // not a stream op -> graph-capture safe.
    cudaFuncSetAttribute(afm_kernel,
                         cudaFuncAttributeMaxDynamicSharedMemorySize,
                         (int)dyn_smem);

    afm_kernel<<<NB, 256, dyn_smem>>>(x, Ww, bw, cross, W1, b1, w2,
                                      Wd1, bd1, Wd2, bd2, Wd3, bd3, Wo, bo,
                                      out);
}

// round 2
// speedup vs baseline: 1.1911x; 1.1911x over previous
#include <cuda_runtime.h>
#include <math.h>

#define NB 512
#define NF 64
#define NK 64

// upper-triangular 8x8 tile enumeration (36 tiles)
__device__ __constant__ unsigned char TI_ARR[36] = {
    0,0,0,0,0,0,0,0,
    1,1,1,1,1,1,1,
    2,2,2,2,2,2,
    3,3,3,3,3,
    4,4,4,4,
    5,5,5,
    6,6,
    7};
__device__ __constant__ unsigned char TJ_ARR[36] = {
    0,1,2,3,4,5,6,7,
    1,2,3,4,5,6,7,
    2,3,4,5,6,7,
    3,4,5,6,7,
    4,5,6,7,
    5,6,7,
    6,7,
    7};

// ---- packed fp32x2 helpers (FFMA2 path, sm_100+) ----
__device__ __forceinline__ unsigned long long f2mul(unsigned long long a,
                                                    unsigned long long b) {
    unsigned long long d;
    asm("mul.rn.f32x2 %0, %1, %2;" : "=l"(d) : "l"(a), "l"(b));
    return d;
}
__device__ __forceinline__ unsigned long long f2fma(unsigned long long a,
                                                    unsigned long long b,
                                                    unsigned long long c) {
    unsigned long long d;
    asm("fma.rn.f32x2 %0, %1, %2, %3;" : "=l"(d) : "l"(a), "l"(b), "l"(c));
    return d;
}
__device__ __forceinline__ float2 f2unpack(unsigned long long p) {
    float2 r;
    asm("mov.b64 {%0,%1}, %2;" : "=f"(r.x), "=f"(r.y) : "l"(p));
    return r;
}

__global__ void __launch_bounds__(256, 2)
afm_kernel(const float* __restrict__ x,
           const float* __restrict__ Ww,  const float* __restrict__ bw,
           const float* __restrict__ cross,
           const float* __restrict__ W1,  const float* __restrict__ b1,
           const float* __restrict__ w2,
           const float* __restrict__ Wd1, const float* __restrict__ bd1,
           const float* __restrict__ Wd2, const float* __restrict__ bd2,
           const float* __restrict__ Wd3, const float* __restrict__ bd3,
           const float* __restrict__ Wo,  const float* __restrict__ bo,
           float* __restrict__ out)
{
    // dynamic smem: u[64][64] then sv[64][64]
    extern __shared__ float dsm[];
    float* u  = dsm;            // u[i*64+k], 16B-aligned rows (64 floats)
    float* sv = dsm + NF * NK;  // scores, then exp-weights

    // W1 stored as float4 tiles with XOR swizzle: row l, float4-col kk at
    // w1s4[l*16 + (kk ^ ((l>>2)&7))]  -> conflict-free vector loads
    __shared__ float4 w1s4[NK * 16];
    __shared__ float xb[NF], b1s[NK], w2s[NK];
    __shared__ float redbuf[8];
    __shared__ float acc4[4][NK];
    __shared__ float tmpv[NK];
    __shared__ float d1s[32], d2s[24], d3s[16];
    __shared__ float m_sh, denom_sh;

    const int b   = blockIdx.x;
    const int tid = threadIdx.x;

    if (tid < NF) {
        xb[tid]  = x[b * NF + tid];
        b1s[tid] = b1[tid];
        w2s[tid] = w2[tid];
    }
    __syncthreads();

    // stage u = x_i * cross_i and swizzled W1 (float4 granularity)
    {
        const float4* W14 = (const float4*)W1;
        const float4* cr4 = (const float4*)cross;
        float4* u4 = (float4*)u;
        for (int idx = tid; idx < NF * 16; idx += 256) {
            int l = idx >> 4, kk = idx & 15;
            w1s4[l * 16 + (kk ^ ((l >> 2) & 7))] = W14[idx];
            float4 c = cr4[idx];
            float s = xb[l];
            float4 uu;
            uu.x = s * c.x; uu.y = s * c.y; uu.z = s * c.z; uu.w = s * c.w;
            u4[idx] = uu;
        }
    }
    __syncthreads();

    // ---------------- Pass 1: attention scores per pair tile ----------------
    // 2 slots of 128 threads; thread = pi(8) x lg(16); each thread covers
    // l = lg*4+q (q=0..3) and all 8 pj, accumulating in f32x2 over k-pairs.
    const int slot = tid >> 7;      // 0..1
    const int t    = tid & 127;
    const int pi   = t >> 4;        // 0..7
    const int lg   = t & 15;        // 0..15
    const int sw   = lg & 7;        // swizzle key: (l>>2)&7 == lg&7 for l=lg*4+q

    for (int tile = slot; tile < 36; tile += 2) {
        const int ti = TI_ARR[tile], tj = TJ_ARR[tile];
        const int i  = ti * 8 + pi;
        const ulonglong2* ui4 = (const ulonglong2*)(u + i * NK);
        const ulonglong2* ujb = (const ulonglong2*)(u + (tj * 8) * NK);
        const ulonglong2* wlb = (const ulonglong2*)&w1s4[(lg * 4) * 16];

        unsigned long long acc2[8][4];
        #pragma unroll
        for (int pj = 0; pj < 8; pj++)
            #pragma unroll
            for (int q = 0; q < 4; q++) acc2[pj][q] = 0ull;

        #pragma unroll 4
        for (int kk = 0; kk < 16; kk++) {
            const ulonglong2 uiv = ui4[kk];
            ulonglong2 wv[4];
            #pragma unroll
            for (int q = 0; q < 4; q++)
                wv[q] = wlb[q * 16 + (kk ^ sw)];
            #pragma unroll
            for (int pj = 0; pj < 8; pj++) {
                const ulonglong2 ujv = ujb[pj * 16 + kk];
                const unsigned long long tx = f2mul(uiv.x, ujv.x);
                const unsigned long long ty = f2mul(uiv.y, ujv.y);
                #pragma unroll
                for (int q = 0; q < 4; q++) {
                    acc2[pj][q] = f2fma(tx, wv[q].x, acc2[pj][q]);
                    acc2[pj][q] = f2fma(ty, wv[q].y, acc2[pj][q]);
                }
            }
        }

        // epilogue: relu(h)+bias, dot with w2 over this thread's 4 l's
        float sp[8];
        #pragma unroll
        for (int pj = 0; pj < 8; pj++) {
            float v = 0.f;
            #pragma unroll
            for (int q = 0; q < 4; q++) {
                float2 ac = f2unpack(acc2[pj][q]);
                float h = fmaxf(ac.x + ac.y + b1s[lg * 4 + q], 0.f);
                v = fmaf(h, w2s[lg * 4 + q], v);
            }
            sp[pj] = v;
        }
        // reduce over the 16 lg lanes (contiguous within half-warp)
        #pragma unroll
        for (int d = 1; d < 16; d <<= 1)
            #pragma unroll
            for (int pj = 0; pj < 8; pj++)
                sp[pj] += __shfl_xor_sync(0xffffffffu, sp[pj], d);

        if (lg == 0) {
            #pragma unroll
            for (int pj = 0; pj < 8; pj++)
                sv[i * NF + tj * 8 + pj] = sp[pj];
        }
    }
    __syncthreads();

    // ---------------- Pass 2: masked softmax ----------------
    float lm = -3.4e38f;
    for (int idx = tid; idx < NF * NF; idx += 256) {
        int i = idx >> 6, j = idx & 63;
        bool valid = (j >= i) && (xb[i] != 0.f) && (xb[j] != 0.f);
        if (valid) lm = fmaxf(lm, sv[idx]);
    }
    #pragma unroll
    for (int d = 16; d; d >>= 1) lm = fmaxf(lm, __shfl_xor_sync(~0u, lm, d));
    if ((tid & 31) == 0) redbuf[tid >> 5] = lm;
    __syncthreads();
    if (tid == 0) {
        float m = 0.f;   // max with the 0-logit seed term
        for (int w = 0; w < 8; w++) m = fmaxf(m, redbuf[w]);
        m_sh = m;
    }
    __syncthreads();
    const float m = m_sh;

    float le = 0.f;
    for (int idx = tid; idx < NF * NF; idx += 256) {
        int i = idx >> 6, j = idx & 63;
        bool valid = (j >= i) && (xb[i] != 0.f) && (xb[j] != 0.f);
        float e = valid ? expf(sv[idx] - m) : 0.f;
        sv[idx] = e;
        le += e;
    }
    #pragma unroll
    for (int d = 16; d; d >>= 1) le += __shfl_xor_sync(~0u, le, d);
    __syncthreads();                 // all sv writes done, redbuf reads done
    if ((tid & 31) == 0) redbuf[tid >> 5] = le;
    __syncthreads();
    if (tid == 0) {
        float tot = expf(-m);        // seed zeros(1) entry
        for (int w = 0; w < 8; w++) tot += redbuf[w];
        denom_sh = tot;
    }
    __syncthreads();

    // ---------------- Pass 3: tmp[k] = sum_ij e_ij * u_i[k]*u_j[k] / denom ----
    {
        const int k = tid & 63, g = tid >> 6;
        float a = 0.f;
        for (int i = g * 16; i < g * 16 + 16; i++) {
            const float* svi = sv + i * NF;
            float w = 0.f;
            #pragma unroll 4
            for (int j = 0; j < NF; j++)
                w = fmaf(svi[j], u[j * NK + k], w);
            a = fmaf(u[i * NK + k], w, a);
        }
        acc4[g][k] = a;
    }
    __syncthreads();
    if (tid < NK)
        tmpv[tid] = (acc4[0][tid] + acc4[1][tid] + acc4[2][tid] + acc4[3][tid])
                    / denom_sh;
    __syncthreads();

    // ---------------- Pass 4: deep MLP 64->32->21->16->1 + sigmoid ----------
    if (tid < 32) {
        float a = bd1[tid];
        const float* w = Wd1 + tid * 64;
        #pragma unroll 4
        for (int j = 0; j < 64; j++) a = fmaf(w[j], tmpv[j], a);
        d1s[tid] = fmaxf(a, 0.f);
    }
    __syncthreads();
    if (tid < 21) {
        float a = bd2[tid];
        const float* w = Wd2 + tid * 32;
        #pragma unroll 4
        for (int j = 0; j < 32; j++) a = fmaf(w[j], d1s[j], a);
        d2s[tid] = fmaxf(a, 0.f);
    }
    __syncthreads();
    if (tid < 16) {
        float a = bd3[tid];
        const float* w = Wd3 + tid * 21;
        for (int j = 0; j < 21; j++) a = fmaf(w[j], d2s[j], a);
        d3s[tid] = fmaxf(a, 0.f);
    }
    __syncthreads();
    if (tid == 0) {
        float o = bo[0];
        #pragma unroll
        for (int j = 0; j < 16; j++) o = fmaf(Wo[j], d3s[j], o);
        float lin = bw[0];
        #pragma unroll 4
        for (int f = 0; f < NF; f++) lin = fmaf(Ww[f], xb[f], lin);
        out[b] = 1.f / (1.f + expf(-(lin + o)));
    }
}

extern "C" void kernel_launch(void* const* d_in, const int* in_sizes, int n_in,
                              void* d_out, int out_size)
{
    const float* x     = (const float*)d_in[0];
    const float* Ww    = (const float*)d_in[1];
    const float* bw    = (const float*)d_in[2];
    const float* cross = (const float*)d_in[3];
    const float* W1    = (const float*)d_in[4];
    const float* b1    = (const float*)d_in[5];
    const float* w2    = (const float*)d_in[6];
    const float* Wd1   = (const float*)d_in[7];
    const float* bd1   = (const float*)d_in[8];
    const float* Wd2   = (const float*)d_in[9];
    const float* bd2   = (const float*)d_in[10];
    const float* Wd3   = (const float*)d_in[11];
    const float* bd3   = (const float*)d_in[12];
    const float* Wo    = (const float*)d_in[13];
    const float* bo    = (const float*)d_in[14];
    float* out = (float*)d_out;

    const size_t dyn_smem = (size_t)(NF * NK + NF * NF) * sizeof(float); // 32 KB
    cudaFuncSetAttribute(afm_kernel,
                         cudaFuncAttributeMaxDynamicSharedMemorySize,
                         (int)dyn_smem);

    afm_kernel<<<NB, 256, dyn_smem>>>(x, Ww, bw, cross, W1, b1, w2,
                                      Wd1, bd1, Wd2, bd2, Wd3, bd3, Wo, bo,
                                      out);
}

// round 4
// speedup vs baseline: 2.3267x; 1.9534x over previous
#include <cuda_runtime.h>
#include <math.h>
#include <stdint.h>

#define NB 512
#define NF 64
#define NK 64
#define US 68            // padded row stride for u / W1 in smem (banks 4r+k)

// upper-triangular 8x8 tile enumeration (36 tiles)
__device__ __constant__ unsigned char TI_ARR[36] = {
    0,0,0,0,0,0,0,0,
    1,1,1,1,1,1,1,
    2,2,2,2,2,2,
    3,3,3,3,3,
    4,4,4,4,
    5,5,5,
    6,6,
    7};
__device__ __constant__ unsigned char TJ_ARR[36] = {
    0,1,2,3,4,5,6,7,
    1,2,3,4,5,6,7,
    2,3,4,5,6,7,
    3,4,5,6,7,
    4,5,6,7,
    5,6,7,
    6,7,
    7};

__device__ __forceinline__ uint32_t to_tf32(float f) {
    uint32_t r;
    asm("cvt.rna.tf32.f32 %0, %1;" : "=r"(r) : "f"(f));
    return r;
}

// D[16x8] += A[16x8](tf32) * B[8x8](tf32, col-major i.e. B[n][k] rows)
__device__ __forceinline__ void mma8(float c[4],
                                     uint32_t a0, uint32_t a1,
                                     uint32_t a2, uint32_t a3,
                                     uint32_t b0, uint32_t b1) {
    asm("mma.sync.aligned.m16n8k8.row.col.f32.tf32.tf32.f32 "
        "{%0,%1,%2,%3}, {%4,%5,%6,%7}, {%8,%9}, {%0,%1,%2,%3};"
        : "+f"(c[0]), "+f"(c[1]), "+f"(c[2]), "+f"(c[3])
        : "r"(a0), "r"(a1), "r"(a2), "r"(a3), "r"(b0), "r"(b1));
}

// dynamic smem (floats): u[64*68] | w1u[64*68] (tf32 bits) | sv[64*64]
#define OFF_U   0
#define OFF_W1  (NF * US)
#define OFF_SV  (2 * NF * US)
#define DSM_FLOATS (2 * NF * US + NF * NF)

__global__ void __launch_bounds__(256, 2)
afm_kernel(const float* __restrict__ x,
           const float* __restrict__ Ww,  const float* __restrict__ bw,
           const float* __restrict__ cross,
           const float* __restrict__ W1,  const float* __restrict__ b1,
           const float* __restrict__ w2,
           const float* __restrict__ Wd1, const float* __restrict__ bd1,
           const float* __restrict__ Wd2, const float* __restrict__ bd2,
           const float* __restrict__ Wd3, const float* __restrict__ bd3,
           const float* __restrict__ Wo,  const float* __restrict__ bo,
           float* __restrict__ out)
{
    extern __shared__ float dsm[];
    float*    u   = dsm + OFF_U;
    uint32_t* w1u = (uint32_t*)(dsm + OFF_W1);
    float*    sv  = dsm + OFF_SV;

    __shared__ float xb[NF], b1s[NK], w2s[NK];
    __shared__ float redbuf[8];
    __shared__ float acc4[4][NK];
    __shared__ float tmpv[NK];
    __shared__ float d1s[32], d2s[24], d3s[16];
    __shared__ float m_sh, denom_sh;

    const int b    = blockIdx.x;
    const int tid  = threadIdx.x;
    const int wid  = tid >> 5;
    const int lane = tid & 31;
    const int grp  = lane >> 2;     // 0..7
    const int qc   = lane & 3;      // 0..3

    if (tid < NF) {
        xb[tid]  = x[b * NF + tid];
        b1s[tid] = b1[tid];
        w2s[tid] = w2[tid];
    }
    __syncthreads();

    // stage u = x_i * cross_i (fp32, padded) and W1 as tf32 bits (padded)
    for (int idx = tid; idx < NF * NK; idx += 256) {
        int r = idx >> 6, c = idx & 63;
        u[r * US + c]   = xb[r] * cross[idx];
        w1u[r * US + c] = to_tf32(W1[idx]);
    }
    __syncthreads();

    // ---------------- Pass 1: attention scores via tf32 mma.sync -----------
    // 72 unit-pairs; pair p = tile t (36) x half h (2); each pair = two m16
    // slabs sharing u_j and B fragments. Warp w handles p = w, w+8, ...
    for (int p = wid; p < 72; p += 8) {
        const int t  = p >> 1;
        const int h  = p & 1;
        const int ib = TI_ARR[t] * 8 + 4 * h;   // i rows ib..ib+3
        const int jb = TJ_ARR[t] * 8;
        const float* uj  = u + (jb + grp) * US;
        const float* ui0 = u + (ib + 0) * US;
        const float* ui1 = u + (ib + 1) * US;
        const float* ui2 = u + (ib + 2) * US;
        const float* ui3 = u + (ib + 3) * US;

        float acc0[8][4], acc1[8][4];
        #pragma unroll
        for (int nt = 0; nt < 8; nt++)
            #pragma unroll
            for (int q = 0; q < 4; q++) { acc0[nt][q] = 0.f; acc1[nt][q] = 0.f; }

        #pragma unroll
        for (int ks = 0; ks < 8; ks++) {
            const int k0 = ks * 8 + qc, k1 = k0 + 4;
            const float uj0 = uj[k0], uj1 = uj[k1];
            // unit0 (rows ib, ib+1), unit1 (rows ib+2, ib+3)
            const uint32_t a00 = to_tf32(ui0[k0] * uj0);
            const uint32_t a01 = to_tf32(ui1[k0] * uj0);
            const uint32_t a02 = to_tf32(ui0[k1] * uj1);
            const uint32_t a03 = to_tf32(ui1[k1] * uj1);
            const uint32_t a10 = to_tf32(ui2[k0] * uj0);
            const uint32_t a11 = to_tf32(ui3[k0] * uj0);
            const uint32_t a12 = to_tf32(ui2[k1] * uj1);
            const uint32_t a13 = to_tf32(ui3[k1] * uj1);
            #pragma unroll
            for (int nt = 0; nt < 8; nt++) {
                const uint32_t* wrow = w1u + (nt * 8 + grp) * US;
                const uint32_t b0 = wrow[k0], b1v = wrow[k1];
                mma8(acc0[nt], a00, a01, a02, a03, b0, b1v);
                mma8(acc1[nt], a10, a11, a12, a13, b0, b1v);
            }
        }

        // epilogue in fragments: relu(S + b1) . w2, thread-local 16 cols,
        // then quad reduce (lanes differing in qc share the same rows)
        float s[4] = {0.f, 0.f, 0.f, 0.f};   // rows ib+0..ib+3
        #pragma unroll
        for (int nt = 0; nt < 8; nt++) {
            #pragma unroll
            for (int d2 = 0; d2 < 2; d2++) {
                const int l = nt * 8 + 2 * qc + d2;
                const float bb = b1s[l], ww = w2s[l];
                s[0] = fmaf(fmaxf(acc0[nt][0 + d2] + bb, 0.f), ww, s[0]);
                s[1] = fmaf(fmaxf(acc0[nt][2 + d2] + bb, 0.f), ww, s[1]);
                s[2] = fmaf(fmaxf(acc1[nt][0 + d2] + bb, 0.f), ww, s[2]);
                s[3] = fmaf(fmaxf(acc1[nt][2 + d2] + bb, 0.f), ww, s[3]);
            }
        }
        #pragma unroll
        for (int d = 1; d <= 2; d <<= 1)
            #pragma unroll
            for (int q = 0; q < 4; q++)
                s[q] += __shfl_xor_sync(0xffffffffu, s[q], d);

        if (qc == 0) {
            const int j = jb + grp;
            sv[(ib + 0) * NF + j] = s[0];
            sv[(ib + 1) * NF + j] = s[1];
            sv[(ib + 2) * NF + j] = s[2];
            sv[(ib + 3) * NF + j] = s[3];
        }
    }
    __syncthreads();

    // ---------------- Pass 2: masked softmax ----------------
    float lm = -3.4e38f;
    for (int idx = tid; idx < NF * NF; idx += 256) {
        int i = idx >> 6, j = idx & 63;
        bool valid = (j >= i) && (xb[i] != 0.f) && (xb[j] != 0.f);
        if (valid) lm = fmaxf(lm, sv[idx]);
    }
    #pragma unroll
    for (int d = 16; d; d >>= 1) lm = fmaxf(lm, __shfl_xor_sync(~0u, lm, d));
    if (lane == 0) redbuf[wid] = lm;
    __syncthreads();
    if (tid == 0) {
        float m = 0.f;   // max with the 0-logit seed term
        for (int w = 0; w < 8; w++) m = fmaxf(m, redbuf[w]);
        m_sh = m;
    }
    __syncthreads();
    const float m = m_sh;

    float le = 0.f;
    for (int idx = tid; idx < NF * NF; idx += 256) {
        int i = idx >> 6, j = idx & 63;
        bool valid = (j >= i) && (xb[i] != 0.f) && (xb[j] != 0.f);
        float e = valid ? expf(sv[idx] - m) : 0.f;
        sv[idx] = e;
        le += e;
    }
    #pragma unroll
    for (int d = 16; d; d >>= 1) le += __shfl_xor_sync(~0u, le, d);
    __syncthreads();
    if (lane == 0) redbuf[wid] = le;
    __syncthreads();
    if (tid == 0) {
        float tot = expf(-m);        // seed zeros(1) entry
        for (int w = 0; w < 8; w++) tot += redbuf[w];
        denom_sh = tot;
    }
    __syncthreads();

    // ---------------- Pass 3: tmp[k] = sum_ij e_ij u_i[k] u_j[k] / denom ----
    {
        const int k = tid & 63, g4 = tid >> 6;
        float a = 0.f;
        for (int i = g4 * 16; i < g4 * 16 + 16; i++) {
            const float* svi = sv + i * NF;
            float w = 0.f;
            #pragma unroll 4
            for (int j = 0; j < NF; j++)
                w = fmaf(svi[j], u[j * US + k], w);
            a = fmaf(u[i * US + k], w, a);
        }
        acc4[g4][k] = a;
    }
    __syncthreads();
    if (tid < NK)
        tmpv[tid] = (acc4[0][tid] + acc4[1][tid] + acc4[2][tid] + acc4[3][tid])
                    / denom_sh;
    __syncthreads();

    // ---------------- Pass 4: deep MLP 64->32->21->16->1 + sigmoid ----------
    if (tid < 32) {
        float a = bd1[tid];
        const float* w = Wd1 + tid * 64;
        #pragma unroll 4
        for (int j = 0; j < 64; j++) a = fmaf(w[j], tmpv[j], a);
        d1s[tid] = fmaxf(a, 0.f);
    }
    __syncthreads();
    if (tid < 21) {
        float a = bd2[tid];
        const float* w = Wd2 + tid * 32;
        #pragma unroll 4
        for (int j = 0; j < 32; j++) a = fmaf(w[j], d1s[j], a);
        d2s[tid] = fmaxf(a, 0.f);
    }
    __syncthreads();
    if (tid < 16) {
        float a = bd3[tid];
        const float* w = Wd3 + tid * 21;
        for (int j = 0; j < 21; j++) a = fmaf(w[j], d2s[j], a);
        d3s[tid] = fmaxf(a, 0.f);
    }
    __syncthreads();
    if (tid == 0) {
        float o = bo[0];
        #pragma unroll
        for (int j = 0; j < 16; j++) o = fmaf(Wo[j], d3s[j], o);
        float lin = bw[0];
        #pragma unroll 4
        for (int f = 0; f < NF; f++) lin = fmaf(Ww[f], xb[f], lin);
        out[b] = 1.f / (1.f + expf(-(lin + o)));
    }
}

extern "C" void kernel_launch(void* const* d_in, const int* in_sizes, int n_in,
                              void* d_out, int out_size)
{
    const float* x     = (const float*)d_in[0];
    const float* Ww    = (const float*)d_in[1];
    const float* bw    = (const float*)d_in[2];
    const float* cross = (const float*)d_in[3];
    const float* W1    = (const float*)d_in[4];
    const float* b1    = (const float*)d_in[5];
    const float* w2    = (const float*)d_in[6];
    const float* Wd1   = (const float*)d_in[7];
    const float* bd1   = (const float*)d_in[8];
    const float* Wd2   = (const float*)d_in[9];
    const float* bd2   = (const float*)d_in[10];
    const float* Wd3   = (const float*)d_in[11];
    const float* bd3   = (const float*)d_in[12];
    const float* Wo    = (const float*)d_in[13];
    const float* bo    = (const float*)d_in[14];
    float* out = (float*)d_out;

    const size_t dyn_smem = (size_t)DSM_FLOATS * sizeof(float); // 51,200 B
    cudaFuncSetAttribute(afm_kernel,
                         cudaFuncAttributeMaxDynamicSharedMemorySize,
                         (int)dyn_smem);

    afm_kernel<<<NB, 256, dyn_smem>>>(x, Ww, bw, cross, W1, b1, w2,
                                      Wd1, bd1, Wd2, bd2, Wd3, bd3, Wo, bo,
                                      out);
}

// round 5
// speedup vs baseline: 3.1886x; 1.3705x over previous
#include <cuda_runtime.h>
#include <math.h>
#include <stdint.h>

#define NB 512
#define NF 64
#define NK 64
#define US 72            // padded row stride (floats) for u / W1 in smem

typedef unsigned long long ull;

// upper-triangular 8x8 tile enumeration (36 tiles)
__device__ __constant__ unsigned char TI_ARR[36] = {
    0,0,0,0,0,0,0,0,
    1,1,1,1,1,1,1,
    2,2,2,2,2,2,
    3,3,3,3,3,
    4,4,4,4,
    5,5,5,
    6,6,
    7};
__device__ __constant__ unsigned char TJ_ARR[36] = {
    0,1,2,3,4,5,6,7,
    1,2,3,4,5,6,7,
    2,3,4,5,6,7,
    3,4,5,6,7,
    4,5,6,7,
    5,6,7,
    6,7,
    7};

__device__ __forceinline__ uint32_t to_tf32(float f) {
    uint32_t r;
    asm("cvt.rna.tf32.f32 %0, %1;" : "=r"(r) : "f"(f));
    return r;
}
__device__ __forceinline__ ull f2mul(ull a, ull b) {
    ull d;
    asm("mul.rn.f32x2 %0, %1, %2;" : "=l"(d) : "l"(a), "l"(b));
    return d;
}
__device__ __forceinline__ void unpk(ull p, uint32_t& lo, uint32_t& hi) {
    asm("mov.b64 {%0,%1}, %2;" : "=r"(lo), "=r"(hi) : "l"(p));
}

// D[16x8] += A[16x8](tf32) * B[8x8](tf32 col-major)
__device__ __forceinline__ void mma8(float c[4],
                                     uint32_t a0, uint32_t a1,
                                     uint32_t a2, uint32_t a3,
                                     uint32_t b0, uint32_t b1) {
    asm("mma.sync.aligned.m16n8k8.row.col.f32.tf32.tf32.f32 "
        "{%0,%1,%2,%3}, {%4,%5,%6,%7}, {%8,%9}, {%0,%1,%2,%3};"
        : "+f"(c[0]), "+f"(c[1]), "+f"(c[2]), "+f"(c[3])
        : "r"(a0), "r"(a1), "r"(a2), "r"(a3), "r"(b0), "r"(b1));
}

// fragment-major position: k=8ks+qc+4h  ->  p=8ks+2qc+h
__device__ __forceinline__ int enc_k(int k) {
    return (k & ~7) | ((k & 3) << 1) | ((k >> 2) & 1);
}
__device__ __forceinline__ int dec_p(int p) {
    return (p & ~7) | ((p >> 1) & 3) | ((p & 1) << 2);
}

// dynamic smem (floats): u[64*72] | w1u[64*72] (tf32 bits) | sv[64*64]
#define OFF_U   0
#define OFF_W1  (NF * US)
#define OFF_SV  (2 * NF * US)
#define DSM_FLOATS (2 * NF * US + NF * NF)

__global__ void __launch_bounds__(256, 2)
afm_kernel(const float* __restrict__ x,
           const float* __restrict__ Ww,  const float* __restrict__ bw,
           const float* __restrict__ cross,
           const float* __restrict__ W1,  const float* __restrict__ b1,
           const float* __restrict__ w2,
           const float* __restrict__ Wd1, const float* __restrict__ bd1,
           const float* __restrict__ Wd2, const float* __restrict__ bd2,
           const float* __restrict__ Wd3, const float* __restrict__ bd3,
           const float* __restrict__ Wo,  const float* __restrict__ bo,
           float* __restrict__ out)
{
    extern __shared__ float dsm[];
    float*    u   = dsm + OFF_U;
    uint32_t* w1u = (uint32_t*)(dsm + OFF_W1);
    float*    sv  = dsm + OFF_SV;

    __shared__ float xb[NF], b1s[NK], w2s[NK];
    __shared__ float redbuf[8];
    __shared__ float acc8[8][NK];
    __shared__ float tmpv[NK];
    __shared__ float d1s[32], d2s[24], d3s[16];
    __shared__ float m_sh, denom_sh;

    const int b    = blockIdx.x;
    const int tid  = threadIdx.x;
    const int wid  = tid >> 5;
    const int lane = tid & 31;
    const int grp  = lane >> 2;     // 0..7
    const int qc   = lane & 3;      // 0..3

    if (tid < NF) {
        xb[tid]  = x[b * NF + tid];
        b1s[tid] = b1[tid];
        w2s[tid] = w2[tid];
    }
    __syncthreads();

    // stage u = x_i * cross_i and W1 (tf32 bits), both fragment-major
    for (int idx = tid; idx < NF * NK; idx += 256) {
        int r = idx >> 6, k = idx & 63;
        int p = enc_k(k);
        u[r * US + p]   = xb[r] * cross[idx];
        w1u[r * US + p] = to_tf32(W1[idx]);
    }
    __syncthreads();

    // ---------------- Pass 1: attention scores via tf32 mma.sync -----------
    // 72 unit-pairs; pair p = tile t (36) x half h (2); warp w: p = w, w+8, ..
    const ull* wb = (const ull*)(w1u + grp * US);   // + nt*288 + 4ks+qc

    for (int p = wid; p < 72; p += 8) {
        const int t  = p >> 1;
        const int h  = p & 1;
        const int ib = TI_ARR[t] * 8 + 4 * h;   // i rows ib..ib+3
        const int jb = TJ_ARR[t] * 8;
        const ull* uj8 = (const ull*)(u + (jb + grp) * US);
        const ull* u80 = (const ull*)(u + (ib + 0) * US);
        const ull* u81 = (const ull*)(u + (ib + 1) * US);
        const ull* u82 = (const ull*)(u + (ib + 2) * US);
        const ull* u83 = (const ull*)(u + (ib + 3) * US);

        float acc0[8][4], acc1[8][4];
        #pragma unroll
        for (int nt = 0; nt < 8; nt++)
            #pragma unroll
            for (int q = 0; q < 4; q++) { acc0[nt][q] = 0.f; acc1[nt][q] = 0.f; }

        #pragma unroll
        for (int ks = 0; ks < 8; ks++) {
            const int o = 4 * ks + qc;
            const ull ujv = uj8[o];
            const ull P0 = f2mul(u80[o], ujv);   // (a00, a02)
            const ull P1 = f2mul(u81[o], ujv);   // (a01, a03)
            const ull P2 = f2mul(u82[o], ujv);   // (a10, a12)
            const ull P3 = f2mul(u83[o], ujv);   // (a11, a13)
            uint32_t a00, a02, a01, a03, a10, a12, a11, a13;
            unpk(P0, a00, a02); unpk(P1, a01, a03);
            unpk(P2, a10, a12); unpk(P3, a11, a13);
            #pragma unroll
            for (int nt = 0; nt < 8; nt++) {
                uint32_t b0, b1v;
                unpk(wb[nt * 288 + o], b0, b1v);
                mma8(acc0[nt], a00, a01, a02, a03, b0, b1v);
                mma8(acc1[nt], a10, a11, a12, a13, b0, b1v);
            }
        }

        // epilogue: relu(S + b1) . w2, thread-local 16 cols, quad reduce
        float s[4] = {0.f, 0.f, 0.f, 0.f};   // rows ib+0..ib+3
        #pragma unroll
        for (int nt = 0; nt < 8; nt++) {
            #pragma unroll
            for (int d2 = 0; d2 < 2; d2++) {
                const int l = nt * 8 + 2 * qc + d2;
                const float bb = b1s[l], ww = w2s[l];
                s[0] = fmaf(fmaxf(acc0[nt][0 + d2] + bb, 0.f), ww, s[0]);
                s[1] = fmaf(fmaxf(acc0[nt][2 + d2] + bb, 0.f), ww, s[1]);
                s[2] = fmaf(fmaxf(acc1[nt][0 + d2] + bb, 0.f), ww, s[2]);
                s[3] = fmaf(fmaxf(acc1[nt][2 + d2] + bb, 0.f), ww, s[3]);
            }
        }
        #pragma unroll
        for (int d = 1; d <= 2; d <<= 1)
            #pragma unroll
            for (int q = 0; q < 4; q++)
                s[q] += __shfl_xor_sync(0xffffffffu, s[q], d);

        if (qc == 0) {
            const int j = jb + grp;
            sv[(ib + 0) * NF + j] = s[0];
            sv[(ib + 1) * NF + j] = s[1];
            sv[(ib + 2) * NF + j] = s[2];
            sv[(ib + 3) * NF + j] = s[3];
        }
    }
    __syncthreads();

    // ---------------- Pass 2: masked softmax ----------------
    float lm = -3.4e38f;
    for (int idx = tid; idx < NF * NF; idx += 256) {
        int i = idx >> 6, j = idx & 63;
        bool valid = (j >= i) && (xb[i] != 0.f) && (xb[j] != 0.f);
        if (valid) lm = fmaxf(lm, sv[idx]);
    }
    #pragma unroll
    for (int d = 16; d; d >>= 1) lm = fmaxf(lm, __shfl_xor_sync(~0u, lm, d));
    if (lane == 0) redbuf[wid] = lm;
    __syncthreads();
    if (tid == 0) {
        float m = 0.f;   // max with the 0-logit seed term
        for (int w = 0; w < 8; w++) m = fmaxf(m, redbuf[w]);
        m_sh = m;
    }
    __syncthreads();
    const float m = m_sh;

    float le = 0.f;
    for (int idx = tid; idx < NF * NF; idx += 256) {
        int i = idx >> 6, j = idx & 63;
        bool valid = (j >= i) && (xb[i] != 0.f) && (xb[j] != 0.f);
        float e = valid ? __expf(sv[idx] - m) : 0.f;
        sv[idx] = e;
        le += e;
    }
    #pragma unroll
    for (int d = 16; d; d >>= 1) le += __shfl_xor_sync(~0u, le, d);
    __syncthreads();
    if (lane == 0) redbuf[wid] = le;
    __syncthreads();
    if (tid == 0) {
        float tot = __expf(-m);      // seed zeros(1) entry
        for (int w = 0; w < 8; w++) tot += redbuf[w];
        denom_sh = tot;
    }
    __syncthreads();

    // ------- Pass 3: tmp[k] = sum_i u_i[k] * (sum_j e_ij u_j[k]) / denom ----
    // lane owns float2 position pair; warp = one i-group of 8
    {
        const int k2 = lane;            // ull position 0..31
        const int g  = wid;             // i-group 0..7
        float wx, wy, ax = 0.f, ay = 0.f;
        for (int i = g * 8; i < g * 8 + 8; i++) {
            const float4* svi4 = (const float4*)(sv + i * NF);
            wx = 0.f; wy = 0.f;
            #pragma unroll 4
            for (int j4 = 0; j4 < 16; j4++) {
                const float4 e4 = svi4[j4];
                const float2* uj = (const float2*)(u + (j4 * 4) * US);
                float2 v0 = uj[k2];
                float2 v1 = ((const float2*)(u + (j4 * 4 + 1) * US))[k2];
                float2 v2 = ((const float2*)(u + (j4 * 4 + 2) * US))[k2];
                float2 v3 = ((const float2*)(u + (j4 * 4 + 3) * US))[k2];
                wx = fmaf(e4.x, v0.x, wx); wy = fmaf(e4.x, v0.y, wy);
                wx = fmaf(e4.y, v1.x, wx); wy = fmaf(e4.y, v1.y, wy);
                wx = fmaf(e4.z, v2.x, wx); wy = fmaf(e4.z, v2.y, wy);
                wx = fmaf(e4.w, v3.x, wx); wy = fmaf(e4.w, v3.y, wy);
            }
            float2 uiv = ((const float2*)(u + i * US))[k2];
            ax = fmaf(uiv.x, wx, ax);
            ay = fmaf(uiv.y, wy, ay);
        }
        acc8[g][2 * k2]     = ax;
        acc8[g][2 * k2 + 1] = ay;
    }
    __syncthreads();
    if (tid < NK) {
        float a = 0.f;
        #pragma unroll
        for (int g = 0; g < 8; g++) a += acc8[g][tid];
        tmpv[dec_p(tid)] = a / denom_sh;
    }
    __syncthreads();

    // ---------------- Pass 4: deep MLP 64->32->21->16->1 + sigmoid ----------
    if (tid < 32) {
        float a = bd1[tid];
        const float* w = Wd1 + tid * 64;
        #pragma unroll 4
        for (int j = 0; j < 64; j++) a = fmaf(w[j], tmpv[j], a);
        d1s[tid] = fmaxf(a, 0.f);
    }
    __syncthreads();
    if (tid < 21) {
        float a = bd2[tid];
        const float* w = Wd2 + tid * 32;
        #pragma unroll 4
        for (int j = 0; j < 32; j++) a = fmaf(w[j], d1s[j], a);
        d2s[tid] = fmaxf(a, 0.f);
    }
    __syncthreads();
    if (tid < 16) {
        float a = bd3[tid];
        const float* w = Wd3 + tid * 21;
        for (int j = 0; j < 21; j++) a = fmaf(w[j], d2s[j], a);
        d3s[tid] = fmaxf(a, 0.f);
    }
    __syncthreads();
    if (tid == 0) {
        float o = bo[0];
        #pragma unroll
        for (int j = 0; j < 16; j++) o = fmaf(Wo[j], d3s[j], o);
        float lin = bw[0];
        #pragma unroll 4
        for (int f = 0; f < NF; f++) lin = fmaf(Ww[f], xb[f], lin);
        out[b] = 1.f / (1.f + __expf(-(lin + o)));
    }
}

extern "C" void kernel_launch(void* const* d_in, const int* in_sizes, int n_in,
                              void* d_out, int out_size)
{
    const float* x     = (const float*)d_in[0];
    const float* Ww    = (const float*)d_in[1];
    const float* bw    = (const float*)d_in[2];
    const float* cross = (const float*)d_in[3];
    const float* W1    = (const float*)d_in[4];
    const float* b1    = (const float*)d_in[5];
    const float* w2    = (const float*)d_in[6];
    const float* Wd1   = (const float*)d_in[7];
    const float* bd1   = (const float*)d_in[8];
    const float* Wd2   = (const float*)d_in[9];
    const float* bd2   = (const float*)d_in[10];
    const float* Wd3   = (const float*)d_in[11];
    const float* bd3   = (const float*)d_in[12];
    const float* Wo    = (const float*)d_in[13];
    const float* bo    = (const float*)d_in[14];
    float* out = (float*)d_out;

    const size_t dyn_smem = (size_t)DSM_FLOATS * sizeof(float); // 53,248 B
    cudaFuncSetAttribute(afm_kernel,
                         cudaFuncAttributeMaxDynamicSharedMemorySize,
                         (int)dyn_smem);

    afm_kernel<<<NB, 256, dyn_smem>>>(x, Ww, bw, cross, W1, b1, w2,
                                      Wd1, bd1, Wd2, bd2, Wd3, bd3, Wo, bo,
                                      out);
}

// round 6
// speedup vs baseline: 3.7726x; 1.1831x over previous
#include <cuda_runtime.h>
#include <math.h>
#include <stdint.h>

#define NB 512
#define NF 64
#define NK 64
#define US 72            // padded row stride (floats); conflict-free per half-warp

typedef unsigned long long ull;

// upper-triangular 8x8 tile enumeration (36 tiles)
__device__ __constant__ unsigned char TI_ARR[36] = {
    0,0,0,0,0,0,0,0,
    1,1,1,1,1,1,1,
    2,2,2,2,2,2,
    3,3,3,3,3,
    4,4,4,4,
    5,5,5,
    6,6,
    7};
__device__ __constant__ unsigned char TJ_ARR[36] = {
    0,1,2,3,4,5,6,7,
    1,2,3,4,5,6,7,
    2,3,4,5,6,7,
    3,4,5,6,7,
    4,5,6,7,
    5,6,7,
    6,7,
    7};

__device__ __forceinline__ uint32_t to_tf32(float f) {
    uint32_t r;
    asm("cvt.rna.tf32.f32 %0, %1;" : "=r"(r) : "f"(f));
    return r;
}
__device__ __forceinline__ ull f2mul(ull a, ull b) {
    ull d;
    asm("mul.rn.f32x2 %0, %1, %2;" : "=l"(d) : "l"(a), "l"(b));
    return d;
}
__device__ __forceinline__ void unpk(ull p, uint32_t& lo, uint32_t& hi) {
    asm("mov.b64 {%0,%1}, %2;" : "=r"(lo), "=r"(hi) : "l"(p));
}

// D[16x8] += A[16x8](tf32) * B[8x8](tf32 col-major)
__device__ __forceinline__ void mma8(float c[4],
                                     uint32_t a0, uint32_t a1,
                                     uint32_t a2, uint32_t a3,
                                     uint32_t b0, uint32_t b1) {
    asm("mma.sync.aligned.m16n8k8.row.col.f32.tf32.tf32.f32 "
        "{%0,%1,%2,%3}, {%4,%5,%6,%7}, {%8,%9}, {%0,%1,%2,%3};"
        : "+f"(c[0]), "+f"(c[1]), "+f"(c[2]), "+f"(c[3])
        : "r"(a0), "r"(a1), "r"(a2), "r"(a3), "r"(b0), "r"(b1));
}

// fragment-major position: k=8ks+qc+4h  ->  p=8ks+2qc+h
__device__ __forceinline__ int enc_k(int k) {
    return (k & ~7) | ((k & 3) << 1) | ((k >> 2) & 1);
}
__device__ __forceinline__ int dec_p(int p) {
    return (p & ~7) | ((p >> 1) & 3) | ((p & 1) << 2);
}

// dynamic smem (floats): u[64*72] | w1u[64*72] | sv0[64*64] | sv1[64*64]
#define OFF_U   0
#define OFF_W1  (NF * US)
#define OFF_SV0 (2 * NF * US)
#define OFF_SV1 (2 * NF * US + NF * NF)
#define DSM_FLOATS (2 * NF * US + 2 * NF * NF)

__global__ void __launch_bounds__(256, 2)
afm_kernel(const float* __restrict__ x,
           const float* __restrict__ Ww,  const float* __restrict__ bw,
           const float* __restrict__ cross,
           const float* __restrict__ W1,  const float* __restrict__ b1,
           const float* __restrict__ w2,
           const float* __restrict__ Wd1, const float* __restrict__ bd1,
           const float* __restrict__ Wd2, const float* __restrict__ bd2,
           const float* __restrict__ Wd3, const float* __restrict__ bd3,
           const float* __restrict__ Wo,  const float* __restrict__ bo,
           float* __restrict__ out)
{
    extern __shared__ float dsm[];
    float*    u   = dsm + OFF_U;
    uint32_t* w1u = (uint32_t*)(dsm + OFF_W1);
    float*    sv0 = dsm + OFF_SV0;
    float*    sv1 = dsm + OFF_SV1;

    __shared__ float xb[NF], b1s[NK], w2s[NK];
    __shared__ float redbuf[8];
    __shared__ float acc8[8][NK];
    __shared__ float tmpv[NK];
    __shared__ float d1s[32], d2s[24], d3s[16];
    __shared__ float m_sh, denom_sh;

    const int b    = blockIdx.x;
    const int tid  = threadIdx.x;
    const int wid  = tid >> 5;
    const int lane = tid & 31;
    const int grp  = lane >> 2;     // 0..7
    const int qc   = lane & 3;      // 0..3

    if (tid < NF) {
        xb[tid]  = x[b * NF + tid];
        b1s[tid] = b1[tid];
        w2s[tid] = w2[tid];
    }
    __syncthreads();

    // stage u = x_i * cross_i and W1 (tf32 bits), both fragment-major
    for (int idx = tid; idx < NF * NK; idx += 256) {
        int r = idx >> 6, k = idx & 63;
        int p = enc_k(k);
        u[r * US + p]   = xb[r] * cross[idx];
        w1u[r * US + p] = to_tf32(W1[idx]);
    }
    __syncthreads();

    // ---------------- Pass 1: attention scores via tf32 mma.sync -----------
    // n-split across warp pairs: nh = wid&1 owns l in [32*nh, 32*nh+32).
    // B fragments for the warp's 4 nt x 8 ks cached in registers (64 regs).
    const int nh = wid & 1;
    const int wp = wid >> 1;        // 0..3

    ull Bc[4][8];
    #pragma unroll
    for (int nt = 0; nt < 4; nt++) {
        const ull* wrow = (const ull*)(w1u + ((nh * 4 + nt) * 8 + grp) * US);
        #pragma unroll
        for (int ks = 0; ks < 8; ks++)
            Bc[nt][ks] = wrow[4 * ks + qc];
    }
    float* svp = nh ? sv1 : sv0;

    for (int p = wp; p < 72; p += 4) {
        const int t  = p >> 1;
        const int h  = p & 1;
        const int ib = TI_ARR[t] * 8 + 4 * h;   // i rows ib..ib+3
        const int jb = TJ_ARR[t] * 8;
        const ull* uj8 = (const ull*)(u + (jb + grp) * US);
        const ull* u80 = (const ull*)(u + (ib + 0) * US);
        const ull* u81 = (const ull*)(u + (ib + 1) * US);
        const ull* u82 = (const ull*)(u + (ib + 2) * US);
        const ull* u83 = (const ull*)(u + (ib + 3) * US);

        float acc0[4][4], acc1[4][4];
        #pragma unroll
        for (int nt = 0; nt < 4; nt++)
            #pragma unroll
            for (int q = 0; q < 4; q++) { acc0[nt][q] = 0.f; acc1[nt][q] = 0.f; }

        #pragma unroll
        for (int ks = 0; ks < 8; ks++) {
            const int o = 4 * ks + qc;
            const ull ujv = uj8[o];
            const ull P0 = f2mul(u80[o], ujv);   // (a00, a02)
            const ull P1 = f2mul(u81[o], ujv);   // (a01, a03)
            const ull P2 = f2mul(u82[o], ujv);   // (a10, a12)
            const ull P3 = f2mul(u83[o], ujv);   // (a11, a13)
            uint32_t a00, a02, a01, a03, a10, a12, a11, a13;
            unpk(P0, a00, a02); unpk(P1, a01, a03);
            unpk(P2, a10, a12); unpk(P3, a11, a13);
            #pragma unroll
            for (int nt = 0; nt < 4; nt++) {
                uint32_t b0, b1v;
                unpk(Bc[nt][ks], b0, b1v);
                mma8(acc0[nt], a00, a01, a02, a03, b0, b1v);
                mma8(acc1[nt], a10, a11, a12, a13, b0, b1v);
            }
        }

        // epilogue: relu(S + b1) . w2 over this warp's 32 l's, quad reduce
        float s[4] = {0.f, 0.f, 0.f, 0.f};   // rows ib+0..ib+3
        #pragma unroll
        for (int nt = 0; nt < 4; nt++) {
            #pragma unroll
            for (int d2 = 0; d2 < 2; d2++) {
                const int l = nh * 32 + nt * 8 + 2 * qc + d2;
                const float bb = b1s[l], ww = w2s[l];
                s[0] = fmaf(fmaxf(acc0[nt][0 + d2] + bb, 0.f), ww, s[0]);
                s[1] = fmaf(fmaxf(acc0[nt][2 + d2] + bb, 0.f), ww, s[1]);
                s[2] = fmaf(fmaxf(acc1[nt][0 + d2] + bb, 0.f), ww, s[2]);
                s[3] = fmaf(fmaxf(acc1[nt][2 + d2] + bb, 0.f), ww, s[3]);
            }
        }
        #pragma unroll
        for (int d = 1; d <= 2; d <<= 1)
            #pragma unroll
            for (int q = 0; q < 4; q++)
                s[q] += __shfl_xor_sync(0xffffffffu, s[q], d);

        if (qc == 0) {
            const int j = jb + grp;
            svp[(ib + 0) * NF + j] = s[0];
            svp[(ib + 1) * NF + j] = s[1];
            svp[(ib + 2) * NF + j] = s[2];
            svp[(ib + 3) * NF + j] = s[3];
        }
    }
    __syncthreads();

    // ---------------- Pass 2: merge halves + masked softmax ----------------
    float sloc[16];
    float lm = -3.4e38f;
    #pragma unroll
    for (int it = 0; it < 16; it++) {
        const int idx = tid + it * 256;
        const int i = idx >> 6, j = idx & 63;
        const float s = sv0[idx] + sv1[idx];
        sloc[it] = s;
        const bool valid = (j >= i) && (xb[i] != 0.f) && (xb[j] != 0.f);
        if (valid) lm = fmaxf(lm, s);
    }
    #pragma unroll
    for (int d = 16; d; d >>= 1) lm = fmaxf(lm, __shfl_xor_sync(~0u, lm, d));
    if (lane == 0) redbuf[wid] = lm;
    __syncthreads();
    if (tid == 0) {
        float m = 0.f;   // max with the 0-logit seed term
        for (int w = 0; w < 8; w++) m = fmaxf(m, redbuf[w]);
        m_sh = m;
    }
    __syncthreads();
    const float m = m_sh;

    float le = 0.f;
    #pragma unroll
    for (int it = 0; it < 16; it++) {
        const int idx = tid + it * 256;
        const int i = idx >> 6, j = idx & 63;
        const bool valid = (j >= i) && (xb[i] != 0.f) && (xb[j] != 0.f);
        const float e = valid ? __expf(sloc[it] - m) : 0.f;
        sv0[idx] = e;
        le += e;
    }
    #pragma unroll
    for (int d = 16; d; d >>= 1) le += __shfl_xor_sync(~0u, le, d);
    __syncthreads();
    if (lane == 0) redbuf[wid] = le;
    __syncthreads();
    if (tid == 0) {
        float tot = __expf(-m);      // seed zeros(1) entry
        for (int w = 0; w < 8; w++) tot += redbuf[w];
        denom_sh = tot;
    }
    __syncthreads();

    // ------- Pass 3: tmp[k] = sum_i u_i[k] * (sum_j e_ij u_j[k]) / denom ----
    // j-outer: u_j loads hoisted out of the i-loop; e read as broadcasts.
    {
        const int k2 = lane;            // float2 position 0..31
        const int g  = wid;             // i-group 0..7
        float wx[8], wy[8];
        #pragma unroll
        for (int i = 0; i < 8; i++) { wx[i] = 0.f; wy[i] = 0.f; }
        const float4* svg = (const float4*)(sv0 + (g * 8) * NF);
        #pragma unroll 2
        for (int j4 = 0; j4 < 16; j4++) {
            const float2 v0 = ((const float2*)(u + (j4 * 4 + 0) * US))[k2];
            const float2 v1 = ((const float2*)(u + (j4 * 4 + 1) * US))[k2];
            const float2 v2 = ((const float2*)(u + (j4 * 4 + 2) * US))[k2];
            const float2 v3 = ((const float2*)(u + (j4 * 4 + 3) * US))[k2];
            #pragma unroll
            for (int i = 0; i < 8; i++) {
                const float4 e4 = svg[i * 16 + j4];
                wx[i] = fmaf(e4.x, v0.x, wx[i]); wy[i] = fmaf(e4.x, v0.y, wy[i]);
                wx[i] = fmaf(e4.y, v1.x, wx[i]); wy[i] = fmaf(e4.y, v1.y, wy[i]);
                wx[i] = fmaf(e4.z, v2.x, wx[i]); wy[i] = fmaf(e4.z, v2.y, wy[i]);
                wx[i] = fmaf(e4.w, v3.x, wx[i]); wy[i] = fmaf(e4.w, v3.y, wy[i]);
            }
        }
        float ax = 0.f, ay = 0.f;
        #pragma unroll
        for (int i = 0; i < 8; i++) {
            const float2 uiv = ((const float2*)(u + (g * 8 + i) * US))[k2];
            ax = fmaf(uiv.x, wx[i], ax);
            ay = fmaf(uiv.y, wy[i], ay);
        }
        acc8[g][2 * k2]     = ax;
        acc8[g][2 * k2 + 1] = ay;
    }
    __syncthreads();
    if (tid < NK) {
        float a = 0.f;
        #pragma unroll
        for (int g = 0; g < 8; g++) a += acc8[g][tid];
        tmpv[dec_p(tid)] = a / denom_sh;
    }
    __syncthreads();

    // ---------------- Pass 4: deep MLP 64->32->21->16->1 + sigmoid ----------
    if (tid < 32) {
        float a = bd1[tid];
        const float* w = Wd1 + tid * 64;
        #pragma unroll 4
        for (int j = 0; j < 64; j++) a = fmaf(w[j], tmpv[j], a);
        d1s[tid] = fmaxf(a, 0.f);
    }
    __syncthreads();
    if (tid < 21) {
        float a = bd2[tid];
        const float* w = Wd2 + tid * 32;
        #pragma unroll 4
        for (int j = 0; j < 32; j++) a = fmaf(w[j], d1s[j], a);
        d2s[tid] = fmaxf(a, 0.f);
    }
    __syncthreads();
    if (tid < 16) {
        float a = bd3[tid];
        const float* w = Wd3 + tid * 21;
        for (int j = 0; j < 21; j++) a = fmaf(w[j], d2s[j], a);
        d3s[tid] = fmaxf(a, 0.f);
    }
    __syncthreads();
    if (tid == 0) {
        float o = bo[0];
        #pragma unroll
        for (int j = 0; j < 16; j++) o = fmaf(Wo[j], d3s[j], o);
        float lin = bw[0];
        #pragma unroll 4
        for (int f = 0; f < NF; f++) lin = fmaf(Ww[f], xb[f], lin);
        out[b] = 1.f / (1.f + __expf(-(lin + o)));
    }
}

extern "C" void kernel_launch(void* const* d_in, const int* in_sizes, int n_in,
                              void* d_out, int out_size)
{
    const float* x     = (const float*)d_in[0];
    const float* Ww    = (const float*)d_in[1];
    const float* bw    = (const float*)d_in[2];
    const float* cross = (const float*)d_in[3];
    const float* W1    = (const float*)d_in[4];
    const float* b1    = (const float*)d_in[5];
    const float* w2    = (const float*)d_in[6];
    const float* Wd1   = (const float*)d_in[7];
    const float* bd1   = (const float*)d_in[8];
    const float* Wd2   = (const float*)d_in[9];
    const float* bd2   = (const float*)d_in[10];
    const float* Wd3   = (const float*)d_in[11];
    const float* bd3   = (const float*)d_in[12];
    const float* Wo    = (const float*)d_in[13];
    const float* bo    = (const float*)d_in[14];
    float* out = (float*)d_out;

    const size_t dyn_smem = (size_t)DSM_FLOATS * sizeof(float); // 69,632 B
    cudaFuncSetAttribute(afm_kernel,
                         cudaFuncAttributeMaxDynamicSharedMemorySize,
                         (int)dyn_smem);

    afm_kernel<<<NB, 256, dyn_smem>>>(x, Ww, bw, cross, W1, b1, w2,
                                      Wd1, bd1, Wd2, bd2, Wd3, bd3, Wo, bo,
                                      out);
}

// round 7
// speedup vs baseline: 3.9836x; 1.0559x over previous
#include <cuda_runtime.h>
#include <math.h>
#include <stdint.h>

#define NB 512
#define NF 64
#define NK 64
#define US 80      // u/w1 row stride (floats)
#define SVS 68     // sv row stride (floats)

typedef unsigned long long ull;

// upper-triangular 8x8 tile enumeration (36 tiles)
__device__ __constant__ unsigned char TI_ARR[36] = {
    0,0,0,0,0,0,0,0,
    1,1,1,1,1,1,1,
    2,2,2,2,2,2,
    3,3,3,3,3,
    4,4,4,4,
    5,5,5,
    6,6,
    7};
__device__ __constant__ unsigned char TJ_ARR[36] = {
    0,1,2,3,4,5,6,7,
    1,2,3,4,5,6,7,
    2,3,4,5,6,7,
    3,4,5,6,7,
    4,5,6,7,
    5,6,7,
    6,7,
    7};

__device__ __forceinline__ uint32_t to_tf32(float f) {
    uint32_t r;
    asm("cvt.rna.tf32.f32 %0, %1;" : "=r"(r) : "f"(f));
    return r;
}
__device__ __forceinline__ ull f2mul(ull a, ull b) {
    ull d;
    asm("mul.rn.f32x2 %0, %1, %2;" : "=l"(d) : "l"(a), "l"(b));
    return d;
}
__device__ __forceinline__ void unpk(ull p, uint32_t& lo, uint32_t& hi) {
    asm("mov.b64 {%0,%1}, %2;" : "=r"(lo), "=r"(hi) : "l"(p));
}

// D[16x8] += A[16x8](tf32) * B[8x8](tf32 col-major)
__device__ __forceinline__ void mma8(float c[4],
                                     uint32_t a0, uint32_t a1,
                                     uint32_t a2, uint32_t a3,
                                     uint32_t b0, uint32_t b1) {
    asm("mma.sync.aligned.m16n8k8.row.col.f32.tf32.tf32.f32 "
        "{%0,%1,%2,%3}, {%4,%5,%6,%7}, {%8,%9}, {%0,%1,%2,%3};"
        : "+f"(c[0]), "+f"(c[1]), "+f"(c[2]), "+f"(c[3])
        : "r"(a0), "r"(a1), "r"(a2), "r"(a3), "r"(b0), "r"(b1));
}

// fragment position within a row: k -> 16*(k>>4) + 4*(k&3) + ((k>>2)&3)
__device__ __forceinline__ int posk(int k) {
    return ((k >> 4) << 4) | ((k & 3) << 2) | ((k >> 2) & 3);
}

// dynamic smem (floats): u[64*80] | w1u[64*80] | sv0[64*68] | sv1[64*68]
#define OFF_U   0
#define OFF_W1  (NF * US)
#define OFF_SV0 (2 * NF * US)
#define OFF_SV1 (2 * NF * US + NF * SVS)
#define DSM_FLOATS (2 * NF * US + 2 * NF * SVS)

__global__ void __launch_bounds__(256, 2)
afm_kernel(const float* __restrict__ x,
           const float* __restrict__ Ww,  const float* __restrict__ bw,
           const float* __restrict__ cross,
           const float* __restrict__ W1,  const float* __restrict__ b1,
           const float* __restrict__ w2,
           const float* __restrict__ Wd1, const float* __restrict__ bd1,
           const float* __restrict__ Wd2, const float* __restrict__ bd2,
           const float* __restrict__ Wd3, const float* __restrict__ bd3,
           const float* __restrict__ Wo,  const float* __restrict__ bo,
           float* __restrict__ out)
{
    extern __shared__ float dsm[];
    float*    u   = dsm + OFF_U;
    uint32_t* w1u = (uint32_t*)(dsm + OFF_W1);
    float*    sv0 = dsm + OFF_SV0;
    float*    sv1 = dsm + OFF_SV1;

    __shared__ float xb[NF], b1s[NK], w2s[NK];
    __shared__ float redbuf[8];
    __shared__ float acc4s[4][NK];
    __shared__ float tmpv[NK];
    __shared__ float d1s[32], d2s[24], d3s[16];
    __shared__ float m_sh, denom_sh;

    const int b    = blockIdx.x;
    const int tid  = threadIdx.x;
    const int wid  = tid >> 5;
    const int lane = tid & 31;
    const int grp  = lane >> 2;     // 0..7
    const int qc   = lane & 3;      // 0..3

    if (tid < NF) {
        xb[tid]  = x[b * NF + tid];
        b1s[tid] = b1[tid];
        w2s[tid] = w2[tid];
    }
    __syncthreads();

    // stage u = x_i * cross_i and W1 (tf32 bits), fragment-major rows
    {
        const float4* cr4 = (const float4*)cross;
        const float4* W14 = (const float4*)W1;
        for (int q4 = tid; q4 < NF * 16; q4 += 256) {
            const int r  = q4 >> 4;
            const int kb = (q4 & 15) << 2;             // k base (mult of 4)
            const int base = r * US + ((kb >> 4) << 4) + ((kb >> 2) & 3);
            const float s = xb[r];
            const float4 c4 = cr4[q4];
            u[base + 0]  = s * c4.x;
            u[base + 4]  = s * c4.y;
            u[base + 8]  = s * c4.z;
            u[base + 12] = s * c4.w;
            const float4 w4 = W14[q4];
            w1u[base + 0]  = to_tf32(w4.x);
            w1u[base + 4]  = to_tf32(w4.y);
            w1u[base + 8]  = to_tf32(w4.z);
            w1u[base + 12] = to_tf32(w4.w);
        }
    }
    __syncthreads();

    // ---------------- Pass 1: attention scores via tf32 mma.sync -----------
    // n-split across warp pairs: nh = wid&1 owns l in [32*nh, 32*nh+32).
    const int nh = wid & 1;
    const int wp = wid >> 1;        // 0..3

    ull Bc[4][8];
    #pragma unroll
    for (int nt = 0; nt < 4; nt++) {
        const uint4* wr = (const uint4*)(w1u + ((nh * 4 + nt) * 8 + grp) * US);
        #pragma unroll
        for (int c = 0; c < 4; c++) {
            const uint4 v = wr[4 * c + qc];
            Bc[nt][2 * c]     = ((ull)v.y << 32) | v.x;
            Bc[nt][2 * c + 1] = ((ull)v.w << 32) | v.z;
        }
    }
    float* svp = nh ? sv1 : sv0;

    for (int p = wp; p < 72; p += 4) {
        const int t  = p >> 1;
        const int h  = p & 1;
        const int ib = TI_ARR[t] * 8 + 4 * h;   // i rows ib..ib+3
        const int jb = TJ_ARR[t] * 8;
        const ulonglong2* uj2 = (const ulonglong2*)(u + (jb + grp) * US);
        const ulonglong2* ua  = (const ulonglong2*)(u + ib * US);  // row=20 u2

        float acc0[4][4], acc1[4][4];
        #pragma unroll
        for (int nt = 0; nt < 4; nt++)
            #pragma unroll
            for (int q = 0; q < 4; q++) { acc0[nt][q] = 0.f; acc1[nt][q] = 0.f; }

        #pragma unroll
        for (int c = 0; c < 4; c++) {
            const int o = 4 * c + qc;
            const ulonglong2 ujv = uj2[o];
            const ulonglong2 r0 = ua[o];
            const ulonglong2 r1 = ua[o + 20];
            const ulonglong2 r2 = ua[o + 40];
            const ulonglong2 r3 = ua[o + 60];
            // ks = 2c products (.x), ks = 2c+1 products (.y)
            const ull P0a = f2mul(r0.x, ujv.x), P0b = f2mul(r0.y, ujv.y);
            const ull P1a = f2mul(r1.x, ujv.x), P1b = f2mul(r1.y, ujv.y);
            const ull P2a = f2mul(r2.x, ujv.x), P2b = f2mul(r2.y, ujv.y);
            const ull P3a = f2mul(r3.x, ujv.x), P3b = f2mul(r3.y, ujv.y);
            uint32_t a00,a02,a01,a03, a10,a12,a11,a13;
            uint32_t c00,c02,c01,c03, c10,c12,c11,c13;
            unpk(P0a, a00, a02); unpk(P1a, a01, a03);
            unpk(P2a, a10, a12); unpk(P3a, a11, a13);
            unpk(P0b, c00, c02); unpk(P1b, c01, c03);
            unpk(P2b, c10, c12); unpk(P3b, c11, c13);
            #pragma unroll
            for (int nt = 0; nt < 4; nt++) {
                uint32_t b0, b1v;
                unpk(Bc[nt][2 * c], b0, b1v);
                mma8(acc0[nt], a00, a01, a02, a03, b0, b1v);
                mma8(acc1[nt], a10, a11, a12, a13, b0, b1v);
                unpk(Bc[nt][2 * c + 1], b0, b1v);
                mma8(acc0[nt], c00, c01, c02, c03, b0, b1v);
                mma8(acc1[nt], c10, c11, c12, c13, b0, b1v);
            }
        }

        // epilogue: relu(S + b1) . w2 over this warp's 32 l's, quad reduce
        float s[4] = {0.f, 0.f, 0.f, 0.f};   // rows ib+0..ib+3
        #pragma unroll
        for (int nt = 0; nt < 4; nt++) {
            #pragma unroll
            for (int d2 = 0; d2 < 2; d2++) {
                const int l = nh * 32 + nt * 8 + 2 * qc + d2;
                const float bb = b1s[l], ww = w2s[l];
                s[0] = fmaf(fmaxf(acc0[nt][0 + d2] + bb, 0.f), ww, s[0]);
                s[1] = fmaf(fmaxf(acc0[nt][2 + d2] + bb, 0.f), ww, s[1]);
                s[2] = fmaf(fmaxf(acc1[nt][0 + d2] + bb, 0.f), ww, s[2]);
                s[3] = fmaf(fmaxf(acc1[nt][2 + d2] + bb, 0.f), ww, s[3]);
            }
        }
        #pragma unroll
        for (int d = 1; d <= 2; d <<= 1)
            #pragma unroll
            for (int q = 0; q < 4; q++)
                s[q] += __shfl_xor_sync(0xffffffffu, s[q], d);

        if (qc == 0) {
            const int j = jb + grp;
            svp[(ib + 0) * SVS + j] = s[0];
            svp[(ib + 1) * SVS + j] = s[1];
            svp[(ib + 2) * SVS + j] = s[2];
            svp[(ib + 3) * SVS + j] = s[3];
        }
    }
    __syncthreads();

    // ---------------- Pass 2: merge halves + masked softmax ----------------
    float sloc[16];
    float lm = -3.4e38f;
    #pragma unroll
    for (int it = 0; it < 16; it++) {
        const int lin = tid + it * 256;
        const int i = lin >> 6, j = lin & 63;
        const int sidx = i * SVS + j;
        const float s = sv0[sidx] + sv1[sidx];
        sloc[it] = s;
        const bool valid = (j >= i) && (xb[i] != 0.f) && (xb[j] != 0.f);
        if (valid) lm = fmaxf(lm, s);
    }
    #pragma unroll
    for (int d = 16; d; d >>= 1) lm = fmaxf(lm, __shfl_xor_sync(~0u, lm, d));
    if (lane == 0) redbuf[wid] = lm;
    __syncthreads();
    if (tid == 0) {
        float m = 0.f;   // max with the 0-logit seed term
        for (int w = 0; w < 8; w++) m = fmaxf(m, redbuf[w]);
        m_sh = m;
    }
    __syncthreads();
    const float m = m_sh;

    float le = 0.f;
    #pragma unroll
    for (int it = 0; it < 16; it++) {
        const int lin = tid + it * 256;
        const int i = lin >> 6, j = lin & 63;
        const bool valid = (j >= i) && (xb[i] != 0.f) && (xb[j] != 0.f);
        // store tf32-truncated e (still a valid fp32 value) so pass 3's MMA
        // sees exactly the weights summed into denom
        float e = valid ? __expf(sloc[it] - m) : 0.f;
        e = __uint_as_float(to_tf32(e));
        sv0[i * SVS + j] = e;
        le += e;
    }
    #pragma unroll
    for (int d = 16; d; d >>= 1) le += __shfl_xor_sync(~0u, le, d);
    __syncthreads();
    if (lane == 0) redbuf[wid] = le;
    __syncthreads();
    if (tid == 0) {
        float tot = __expf(-m);      // seed zeros(1) entry
        for (int w = 0; w < 8; w++) tot += redbuf[w];
        denom_sh = tot;
    }
    __syncthreads();

    // -------- Pass 3: V = E @ U via mma; tmp[k] = sum_i u[i,k] V[i,k] ------
    // M = i (64), N = k (64), K = j (64). warp: mt = wid>>1, 4 n-tiles.
    {
        const int mt    = wid >> 1;            // 0..3
        const int nbase = (wid & 1) * 4;       // n-tiles nbase..nbase+3

        float vacc[4][4];
        #pragma unroll
        for (int cc = 0; cc < 4; cc++)
            #pragma unroll
            for (int q = 0; q < 4; q++) vacc[cc][q] = 0.f;

        int pkb[4];
        #pragma unroll
        for (int cc = 0; cc < 4; cc++)
            pkb[cc] = posk(8 * (nbase + cc) + grp);

        const float* e0 = sv0 + (16 * mt + grp) * SVS;
        const float* e1 = sv0 + (16 * mt + grp + 8) * SVS;

        #pragma unroll
        for (int js = 0; js < 8; js++) {
            const int jc = 8 * js + qc;
            const uint32_t a0 = __float_as_uint(e0[jc]);
            const uint32_t a1 = __float_as_uint(e1[jc]);
            const uint32_t a2 = __float_as_uint(e0[jc + 4]);
            const uint32_t a3 = __float_as_uint(e1[jc + 4]);
            const float* uj0 = u + jc * US;
            const float* uj1 = u + (jc + 4) * US;
            #pragma unroll
            for (int cc = 0; cc < 4; cc++) {
                const uint32_t b0 = __float_as_uint(uj0[pkb[cc]]);
                const uint32_t b1v = __float_as_uint(uj1[pkb[cc]]);
                mma8(vacc[cc], a0, a1, a2, a3, b0, b1v);
            }
        }

        // tmp partials: lane holds V at (i=16mt+grp{,+8}, k=8nt+2qc{,+1})
        float part[8];
        #pragma unroll
        for (int cc = 0; cc < 4; cc++) {
            const int k0 = 8 * (nbase + cc) + 2 * qc;
            const int i0 = 16 * mt + grp;
            const float u00 = u[i0 * US + posk(k0)];
            const float u01 = u[i0 * US + posk(k0 + 1)];
            const float u10 = u[(i0 + 8) * US + posk(k0)];
            const float u11 = u[(i0 + 8) * US + posk(k0 + 1)];
            part[2 * cc]     = fmaf(vacc[cc][0], u00, vacc[cc][2] * u10);
            part[2 * cc + 1] = fmaf(vacc[cc][1], u01, vacc[cc][3] * u11);
        }
        // reduce over grp (lane bits 2..4)
        #pragma unroll
        for (int d = 4; d <= 16; d <<= 1)
            #pragma unroll
            for (int q = 0; q < 8; q++)
                part[q] += __shfl_xor_sync(0xffffffffu, part[q], d);

        if (grp == 0) {   // lanes 0..3 (lane == qc)
            #pragma unroll
            for (int cc = 0; cc < 4; cc++) {
                const int k0 = 8 * (nbase + cc) + 2 * qc;
                acc4s[mt][k0]     = part[2 * cc];
                acc4s[mt][k0 + 1] = part[2 * cc + 1];
            }
        }
    }
    __syncthreads();
    if (tid < NK)
        tmpv[tid] = (acc4s[0][tid] + acc4s[1][tid] +
                     acc4s[2][tid] + acc4s[3][tid]) / denom_sh;
    __syncthreads();

    // ---------------- Pass 4: deep MLP 64->32->21->16->1 + sigmoid ----------
    if (tid < 32) {
        float a = bd1[tid];
        const float* w = Wd1 + tid * 64;
        #pragma unroll 4
        for (int j = 0; j < 64; j++) a = fmaf(w[j], tmpv[j], a);
        d1s[tid] = fmaxf(a, 0.f);
    }
    __syncthreads();
    if (tid < 21) {
        float a = bd2[tid];
        const float* w = Wd2 + tid * 32;
        #pragma unroll 4
        for (int j = 0; j < 32; j++) a = fmaf(w[j], d1s[j], a);
        d2s[tid] = fmaxf(a, 0.f);
    }
    __syncthreads();
    if (tid < 16) {
        float a = bd3[tid];
        const float* w = Wd3 + tid * 21;
        for (int j = 0; j < 21; j++) a = fmaf(w[j], d2s[j], a);
        d3s[tid] = fmaxf(a, 0.f);
    }
    __syncthreads();
    if (tid == 0) {
        float o = bo[0];
        #pragma unroll
        for (int j = 0; j < 16; j++) o = fmaf(Wo[j], d3s[j], o);
        float lin = bw[0];
        #pragma unroll 4
        for (int f = 0; f < NF; f++) lin = fmaf(Ww[f], xb[f], lin);
        out[b] = 1.f / (1.f + __expf(-(lin + o)));
    }
}

extern "C" void kernel_launch(void* const* d_in, const int* in_sizes, int n_in,
                              void* d_out, int out_size)
{
    const float* x     = (const float*)d_in[0];
    const float* Ww    = (const float*)d_in[1];
    const float* bw    = (const float*)d_in[2];
    const float* cross = (const float*)d_in[3];
    const float* W1    = (const float*)d_in[4];
    const float* b1    = (const float*)d_in[5];
    const float* w2    = (const float*)d_in[6];
    const float* Wd1   = (const float*)d_in[7];
    const float* bd1   = (const float*)d_in[8];
    const float* Wd2   = (const float*)d_in[9];
    const float* bd2   = (const float*)d_in[10];
    const float* Wd3   = (const float*)d_in[11];
    const float* bd3   = (const float*)d_in[12];
    const float* Wo    = (const float*)d_in[13];
    const float* bo    = (const float*)d_in[14];
    float* out = (float*)d_out;

    const size_t dyn_smem = (size_t)DSM_FLOATS * sizeof(float); // 75,776 B
    cudaFuncSetAttribute(afm_kernel,
                         cudaFuncAttributeMaxDynamicSharedMemorySize,
                         (int)dyn_smem);

    afm_kernel<<<NB, 256, dyn_smem>>>(x, Ww, bw, cross, W1, b1, w2,
                                      Wd1, bd1, Wd2, bd2, Wd3, bd3, Wo, bo,
                                      out);
}

// round 8
// speedup vs baseline: 6.0144x; 1.5098x over previous
#include <cuda_runtime.h>
#include <cuda_fp16.h>
#include <math.h>
#include <stdint.h>

#define NB 512
#define NF 64
#define NK 64
#define US 80      // u32 row stride (floats)
#define UHS 80     // u16/w1h row stride (halves) -> conflict-free lds.64
#define SVS 68     // sv row stride (floats)

typedef unsigned long long ull;

// upper-triangular 8x8 tile enumeration (36 tiles)
__device__ __constant__ unsigned char TI_ARR[36] = {
    0,0,0,0,0,0,0,0,
    1,1,1,1,1,1,1,
    2,2,2,2,2,2,
    3,3,3,3,3,
    4,4,4,4,
    5,5,5,
    6,6,
    7};
__device__ __constant__ unsigned char TJ_ARR[36] = {
    0,1,2,3,4,5,6,7,
    1,2,3,4,5,6,7,
    2,3,4,5,6,7,
    3,4,5,6,7,
    4,5,6,7,
    5,6,7,
    6,7,
    7};

__device__ __forceinline__ uint32_t to_tf32(float f) {
    uint32_t r;
    asm("cvt.rna.tf32.f32 %0, %1;" : "=r"(r) : "f"(f));
    return r;
}
__device__ __forceinline__ uint32_t hmul2(uint32_t a, uint32_t b) {
    uint32_t d;
    asm("mul.rn.f16x2 %0, %1, %2;" : "=r"(d) : "r"(a), "r"(b));
    return d;
}

// D[16x8] += A[16x16](f16) * B[16x8](f16 col-major), f32 accum
__device__ __forceinline__ void mma16(float c[4],
                                      uint32_t a0, uint32_t a1,
                                      uint32_t a2, uint32_t a3,
                                      uint32_t b0, uint32_t b1) {
    asm("mma.sync.aligned.m16n8k16.row.col.f32.f16.f16.f32 "
        "{%0,%1,%2,%3}, {%4,%5,%6,%7}, {%8,%9}, {%0,%1,%2,%3};"
        : "+f"(c[0]), "+f"(c[1]), "+f"(c[2]), "+f"(c[3])
        : "r"(a0), "r"(a1), "r"(a2), "r"(a3), "r"(b0), "r"(b1));
}
// D[16x8] += A[16x8](tf32) * B[8x8](tf32 col-major)  (pass 3)
__device__ __forceinline__ void mma8(float c[4],
                                     uint32_t a0, uint32_t a1,
                                     uint32_t a2, uint32_t a3,
                                     uint32_t b0, uint32_t b1) {
    asm("mma.sync.aligned.m16n8k8.row.col.f32.tf32.tf32.f32 "
        "{%0,%1,%2,%3}, {%4,%5,%6,%7}, {%8,%9}, {%0,%1,%2,%3};"
        : "+f"(c[0]), "+f"(c[1]), "+f"(c[2]), "+f"(c[3])
        : "r"(a0), "r"(a1), "r"(a2), "r"(a3), "r"(b0), "r"(b1));
}

// f32 fragment position (pass 3): k -> 16*(k>>4) + 4*(k&3) + ((k>>2)&3)
__device__ __forceinline__ int posk(int k) {
    return ((k >> 4) << 4) | ((k & 3) << 2) | ((k >> 2) & 3);
}

// dynamic smem (floats):
//   u32[64*80] | u16[64*80 halves] | w1h[64*80 halves] | sv0 | sv1
#define OFF_U32 0
#define OFF_U16 (NF * US)                       // 5120
#define OFF_W1H (OFF_U16 + NF * UHS / 2)        // 7680
#define OFF_SV0 (OFF_W1H + NF * UHS / 2)        // 10240
#define OFF_SV1 (OFF_SV0 + NF * SVS)            // 14592
#define DSM_FLOATS (OFF_SV1 + NF * SVS)         // 18944 -> 75776 B

__global__ void __launch_bounds__(256, 2)
afm_kernel(const float* __restrict__ x,
           const float* __restrict__ Ww,  const float* __restrict__ bw,
           const float* __restrict__ cross,
           const float* __restrict__ W1,  const float* __restrict__ b1,
           const float* __restrict__ w2,
           const float* __restrict__ Wd1, const float* __restrict__ bd1,
           const float* __restrict__ Wd2, const float* __restrict__ bd2,
           const float* __restrict__ Wd3, const float* __restrict__ bd3,
           const float* __restrict__ Wo,  const float* __restrict__ bo,
           float* __restrict__ out)
{
    extern __shared__ float dsm[];
    float*   u    = dsm + OFF_U32;
    __half*  u16p = (__half*)(dsm + OFF_U16);
    __half*  w1p  = (__half*)(dsm + OFF_W1H);
    float*   sv0  = dsm + OFF_SV0;
    float*   sv1  = dsm + OFF_SV1;

    __shared__ float xb[NF], b1s[NK], w2s[NK];
    __shared__ float redbuf[8];
    __shared__ float acc4s[4][NK];
    __shared__ float tmpv[NK];
    __shared__ float d1s[32], d2s[24], d3s[16];
    __shared__ float m_sh, denom_sh;

    const int b    = blockIdx.x;
    const int tid  = threadIdx.x;
    const int wid  = tid >> 5;
    const int lane = tid & 31;
    const int grp  = lane >> 2;     // 0..7
    const int qc   = lane & 3;      // 0..3

    if (tid < NF) {
        xb[tid]  = x[b * NF + tid];
        b1s[tid] = b1[tid];
        w2s[tid] = w2[tid];
    }
    __syncthreads();

    // stage u (fp32 fragment-major for pass3) + u16/W1 (fp16 fragment-major)
    {
        const float4* cr4 = (const float4*)cross;
        const float4* W14 = (const float4*)W1;
        __half2* u16h = (__half2*)u16p;
        __half2* w1h2 = (__half2*)w1p;
        for (int q4 = tid; q4 < NF * 16; q4 += 256) {
            const int r  = q4 >> 4;
            const int c4 = q4 & 15;
            const float s = xb[r];
            const float4 cc = cr4[q4];
            float4 uu;
            uu.x = s*cc.x; uu.y = s*cc.y; uu.z = s*cc.z; uu.w = s*cc.w;
            // u32: posk layout, row stride 80 floats
            const int kb = c4 << 2;
            const int b32 = r * US + ((kb >> 4) << 4) + ((kb >> 2) & 3);
            u[b32 + 0]  = uu.x;
            u[b32 + 4]  = uu.y;
            u[b32 + 8]  = uu.z;
            u[b32 + 12] = uu.w;
            // fp16: k=16s+8h+2q+d stored at 16s+4q+2h+d (halves), stride 80
            const int hidx = r * (UHS / 2) + 8 * (c4 >> 2) + 4 * (c4 & 1)
                             + ((c4 >> 1) & 1);
            u16h[hidx]     = __floats2half2_rn(uu.x, uu.y);
            u16h[hidx + 2] = __floats2half2_rn(uu.z, uu.w);
            const float4 w4 = W14[q4];
            w1h2[hidx]     = __floats2half2_rn(w4.x, w4.y);
            w1h2[hidx + 2] = __floats2half2_rn(w4.z, w4.w);
        }
    }
    __syncthreads();

    // ---------------- Pass 1: attention scores via fp16 mma.sync -----------
    // n-split across warp pairs: nh = wid&1 owns l in [32*nh, 32*nh+32).
    const int nh = wid & 1;
    const int wp = wid >> 1;        // 0..3

    uint2 Bc[4][4];                 // [nt][k16-step] -> (b0, b1)
    #pragma unroll
    for (int nt = 0; nt < 4; nt++) {
        const uint2* wr = (const uint2*)(w1p + ((nh * 4 + nt) * 8 + grp) * UHS);
        #pragma unroll
        for (int s = 0; s < 4; s++)
            Bc[nt][s] = wr[4 * s + qc];
    }
    float* svp = nh ? sv1 : sv0;

    for (int p = wp; p < 72; p += 4) {
        const int t  = p >> 1;
        const int h  = p & 1;
        const int ib = TI_ARR[t] * 8 + 4 * h;   // i rows ib..ib+3
        const int jb = TJ_ARR[t] * 8;
        const uint2* uj2 = (const uint2*)(u16p + (jb + grp) * UHS);
        const uint2* ui0 = (const uint2*)(u16p + (ib + 0) * UHS);
        const uint2* ui1 = (const uint2*)(u16p + (ib + 1) * UHS);
        const uint2* ui2 = (const uint2*)(u16p + (ib + 2) * UHS);
        const uint2* ui3 = (const uint2*)(u16p + (ib + 3) * UHS);

        float acc0[4][4], acc1[4][4];
        #pragma unroll
        for (int nt = 0; nt < 4; nt++)
            #pragma unroll
            for (int q = 0; q < 4; q++) { acc0[nt][q] = 0.f; acc1[nt][q] = 0.f; }

        #pragma unroll
        for (int s = 0; s < 4; s++) {
            const int o = 4 * s + qc;
            const uint2 uj = uj2[o];
            const uint2 r0 = ui0[o];
            const uint2 r1 = ui1[o];
            const uint2 r2 = ui2[o];
            const uint2 r3 = ui3[o];
            // acc0: rows (j=grp, i=ib) and (j=grp, i=ib+1)
            const uint32_t a0 = hmul2(r0.x, uj.x);
            const uint32_t a1 = hmul2(r1.x, uj.x);
            const uint32_t a2 = hmul2(r0.y, uj.y);
            const uint32_t a3 = hmul2(r1.y, uj.y);
            // acc1: i = ib+2, ib+3
            const uint32_t c0 = hmul2(r2.x, uj.x);
            const uint32_t c1 = hmul2(r3.x, uj.x);
            const uint32_t c2 = hmul2(r2.y, uj.y);
            const uint32_t c3 = hmul2(r3.y, uj.y);
            #pragma unroll
            for (int nt = 0; nt < 4; nt++) {
                mma16(acc0[nt], a0, a1, a2, a3, Bc[nt][s].x, Bc[nt][s].y);
                mma16(acc1[nt], c0, c1, c2, c3, Bc[nt][s].x, Bc[nt][s].y);
            }
        }

        // epilogue: relu(S + b1) . w2 over this warp's 32 l's, quad reduce
        float s4[4] = {0.f, 0.f, 0.f, 0.f};   // rows ib+0..ib+3
        #pragma unroll
        for (int nt = 0; nt < 4; nt++) {
            #pragma unroll
            for (int d2 = 0; d2 < 2; d2++) {
                const int l = nh * 32 + nt * 8 + 2 * qc + d2;
                const float bb = b1s[l], ww = w2s[l];
                s4[0] = fmaf(fmaxf(acc0[nt][0 + d2] + bb, 0.f), ww, s4[0]);
                s4[1] = fmaf(fmaxf(acc0[nt][2 + d2] + bb, 0.f), ww, s4[1]);
                s4[2] = fmaf(fmaxf(acc1[nt][0 + d2] + bb, 0.f), ww, s4[2]);
                s4[3] = fmaf(fmaxf(acc1[nt][2 + d2] + bb, 0.f), ww, s4[3]);
            }
        }
        #pragma unroll
        for (int d = 1; d <= 2; d <<= 1)
            #pragma unroll
            for (int q = 0; q < 4; q++)
                s4[q] += __shfl_xor_sync(0xffffffffu, s4[q], d);

        if (qc == 0) {
            const int j = jb + grp;
            svp[(ib + 0) * SVS + j] = s4[0];
            svp[(ib + 1) * SVS + j] = s4[1];
            svp[(ib + 2) * SVS + j] = s4[2];
            svp[(ib + 3) * SVS + j] = s4[3];
        }
    }
    __syncthreads();

    // ---------------- Pass 2: merge halves + masked softmax ----------------
    float sloc[16];
    float lm = -3.4e38f;
    #pragma unroll
    for (int it = 0; it < 16; it++) {
        const int lin = tid + it * 256;
        const int i = lin >> 6, j = lin & 63;
        const int sidx = i * SVS + j;
        const float s = sv0[sidx] + sv1[sidx];
        sloc[it] = s;
        const bool valid = (j >= i) && (xb[i] != 0.f) && (xb[j] != 0.f);
        if (valid) lm = fmaxf(lm, s);
    }
    #pragma unroll
    for (int d = 16; d; d >>= 1) lm = fmaxf(lm, __shfl_xor_sync(~0u, lm, d));
    if (lane == 0) redbuf[wid] = lm;
    __syncthreads();
    if (tid == 0) {
        float m = 0.f;   // max with the 0-logit seed term
        for (int w = 0; w < 8; w++) m = fmaxf(m, redbuf[w]);
        m_sh = m;
    }
    __syncthreads();
    const float m = m_sh;

    float le = 0.f;
    #pragma unroll
    for (int it = 0; it < 16; it++) {
        const int lin = tid + it * 256;
        const int i = lin >> 6, j = lin & 63;
        const bool valid = (j >= i) && (xb[i] != 0.f) && (xb[j] != 0.f);
        float e = valid ? __expf(sloc[it] - m) : 0.f;
        e = __uint_as_float(to_tf32(e));   // exactly what pass 3's MMA sees
        sv0[i * SVS + j] = e;
        le += e;
    }
    #pragma unroll
    for (int d = 16; d; d >>= 1) le += __shfl_xor_sync(~0u, le, d);
    __syncthreads();
    if (lane == 0) redbuf[wid] = le;
    __syncthreads();
    if (tid == 0) {
        float tot = __expf(-m);      // seed zeros(1) entry
        for (int w = 0; w < 8; w++) tot += redbuf[w];
        denom_sh = tot;
    }
    __syncthreads();

    // -------- Pass 3: V = E @ U via tf32 mma; tmp[k] = sum_i u[i,k] V[i,k] --
    {
        const int mt    = wid >> 1;            // 0..3
        const int nbase = (wid & 1) * 4;       // n-tiles nbase..nbase+3

        float vacc[4][4];
        #pragma unroll
        for (int cc = 0; cc < 4; cc++)
            #pragma unroll
            for (int q = 0; q < 4; q++) vacc[cc][q] = 0.f;

        int pkb[4];
        #pragma unroll
        for (int cc = 0; cc < 4; cc++)
            pkb[cc] = posk(8 * (nbase + cc) + grp);

        const float* e0 = sv0 + (16 * mt + grp) * SVS;
        const float* e1 = sv0 + (16 * mt + grp + 8) * SVS;

        #pragma unroll
        for (int js = 0; js < 8; js++) {
            const int jc = 8 * js + qc;
            const uint32_t a0 = __float_as_uint(e0[jc]);
            const uint32_t a1 = __float_as_uint(e1[jc]);
            const uint32_t a2 = __float_as_uint(e0[jc + 4]);
            const uint32_t a3 = __float_as_uint(e1[jc + 4]);
            const float* uj0 = u + jc * US;
            const float* uj1 = u + (jc + 4) * US;
            #pragma unroll
            for (int cc = 0; cc < 4; cc++) {
                const uint32_t b0 = __float_as_uint(uj0[pkb[cc]]);
                const uint32_t b1v = __float_as_uint(uj1[pkb[cc]]);
                mma8(vacc[cc], a0, a1, a2, a3, b0, b1v);
            }
        }

        float part[8];
        #pragma unroll
        for (int cc = 0; cc < 4; cc++) {
            const int k0 = 8 * (nbase + cc) + 2 * qc;
            const int i0 = 16 * mt + grp;
            const float u00 = u[i0 * US + posk(k0)];
            const float u01 = u[i0 * US + posk(k0 + 1)];
            const float u10 = u[(i0 + 8) * US + posk(k0)];
            const float u11 = u[(i0 + 8) * US + posk(k0 + 1)];
            part[2 * cc]     = fmaf(vacc[cc][0], u00, vacc[cc][2] * u10);
            part[2 * cc + 1] = fmaf(vacc[cc][1], u01, vacc[cc][3] * u11);
        }
        #pragma unroll
        for (int d = 4; d <= 16; d <<= 1)
            #pragma unroll
            for (int q = 0; q < 8; q++)
                part[q] += __shfl_xor_sync(0xffffffffu, part[q], d);

        if (grp == 0) {   // lanes 0..3 (lane == qc)
            #pragma unroll
            for (int cc = 0; cc < 4; cc++) {
                const int k0 = 8 * (nbase + cc) + 2 * qc;
                acc4s[mt][k0]     = part[2 * cc];
                acc4s[mt][k0 + 1] = part[2 * cc + 1];
            }
        }
    }
    __syncthreads();
    if (tid < NK)
        tmpv[tid] = (acc4s[0][tid] + acc4s[1][tid] +
                     acc4s[2][tid] + acc4s[3][tid]) / denom_sh;
    __syncthreads();

    // ---------------- Pass 4: deep MLP 64->32->21->16->1 + sigmoid ----------
    if (tid < 32) {
        float a = bd1[tid];
        const float* w = Wd1 + tid * 64;
        #pragma unroll 4
        for (int j = 0; j < 64; j++) a = fmaf(w[j], tmpv[j], a);
        d1s[tid] = fmaxf(a, 0.f);
    }
    __syncthreads();
    if (tid < 21) {
        float a = bd2[tid];
        const float* w = Wd2 + tid * 32;
        #pragma unroll 4
        for (int j = 0; j < 32; j++) a = fmaf(w[j], d1s[j], a);
        d2s[tid] = fmaxf(a, 0.f);
    }
    __syncthreads();
    if (tid < 16) {
        float a = bd3[tid];
        const float* w = Wd3 + tid * 21;
        for (int j = 0; j < 21; j++) a = fmaf(w[j], d2s[j], a);
        d3s[tid] = fmaxf(a, 0.f);
    }
    __syncthreads();
    if (tid == 0) {
        float o = bo[0];
        #pragma unroll
        for (int j = 0; j < 16; j++) o = fmaf(Wo[j], d3s[j], o);
        float lin = bw[0];
        #pragma unroll 4
        for (int f = 0; f < NF; f++) lin = fmaf(Ww[f], xb[f], lin);
        out[b] = 1.f / (1.f + __expf(-(lin + o)));
    }
}

extern "C" void kernel_launch(void* const* d_in, const int* in_sizes, int n_in,
                              void* d_out, int out_size)
{
    const float* x     = (const float*)d_in[0];
    const float* Ww    = (const float*)d_in[1];
    const float* bw    = (const float*)d_in[2];
    const float* cross = (const float*)d_in[3];
    const float* W1    = (const float*)d_in[4];
    const float* b1    = (const float*)d_in[5];
    const float* w2    = (const float*)d_in[6];
    const float* Wd1   = (const float*)d_in[7];
    const float* bd1   = (const float*)d_in[8];
    const float* Wd2   = (const float*)d_in[9];
    const float* bd2   = (const float*)d_in[10];
    const float* Wd3   = (const float*)d_in[11];
    const float* bd3   = (const float*)d_in[12];
    const float* Wo    = (const float*)d_in[13];
    const float* bo    = (const float*)d_in[14];
    float* out = (float*)d_out;

    const size_t dyn_smem = (size_t)DSM_FLOATS * sizeof(float); // 75,776 B
    cudaFuncSetAttribute(afm_kernel,
                         cudaFuncAttributeMaxDynamicSharedMemorySize,
                         (int)dyn_smem);

    afm_kernel<<<NB, 256, dyn_smem>>>(x, Ww, bw, cross, W1, b1, w2,
                                      Wd1, bd1, Wd2, bd2, Wd3, bd3, Wo, bo,
                                      out);
}

// round 9
// speedup vs baseline: 6.6972x; 1.1135x over previous
#include <cuda_runtime.h>
#include <cuda_fp16.h>
#include <math.h>
#include <stdint.h>

#define NB 512
#define NF 64
#define NK 64
#define US 80      // u32 row stride (floats)
#define UHS 80     // u16/w1h row stride (halves) -> conflict-free lds.64
#define SVS 68     // sv row stride (floats)

typedef unsigned long long ull;

// upper-triangular 8x8 tile enumeration (36 tiles)
__device__ __constant__ unsigned char TI_ARR[36] = {
    0,0,0,0,0,0,0,0,
    1,1,1,1,1,1,1,
    2,2,2,2,2,2,
    3,3,3,3,3,
    4,4,4,4,
    5,5,5,
    6,6,
    7};
__device__ __constant__ unsigned char TJ_ARR[36] = {
    0,1,2,3,4,5,6,7,
    1,2,3,4,5,6,7,
    2,3,4,5,6,7,
    3,4,5,6,7,
    4,5,6,7,
    5,6,7,
    6,7,
    7};

__device__ __forceinline__ uint32_t to_tf32(float f) {
    uint32_t r;
    asm("cvt.rna.tf32.f32 %0, %1;" : "=r"(r) : "f"(f));
    return r;
}
__device__ __forceinline__ uint32_t hmul2(uint32_t a, uint32_t b) {
    uint32_t d;
    asm("mul.rn.f16x2 %0, %1, %2;" : "=r"(d) : "r"(a), "r"(b));
    return d;
}
// pack two f32 -> f16x2 (lo, hi)
__device__ __forceinline__ uint32_t packh2(float lo, float hi) {
    uint32_t d;
    asm("cvt.rn.f16x2.f32 %0, %1, %2;" : "=r"(d) : "f"(hi), "f"(lo));
    return d;
}
// fused relu + pack
__device__ __forceinline__ uint32_t packh2_relu(float lo, float hi) {
    uint32_t d;
    asm("cvt.rn.relu.f16x2.f32 %0, %1, %2;" : "=r"(d) : "f"(hi), "f"(lo));
    return d;
}

// D[16x8] += A[16x16](f16) * B[16x8](f16 col-major), f32 accum
__device__ __forceinline__ void mma16(float c[4],
                                      uint32_t a0, uint32_t a1,
                                      uint32_t a2, uint32_t a3,
                                      uint32_t b0, uint32_t b1) {
    asm("mma.sync.aligned.m16n8k16.row.col.f32.f16.f16.f32 "
        "{%0,%1,%2,%3}, {%4,%5,%6,%7}, {%8,%9}, {%0,%1,%2,%3};"
        : "+f"(c[0]), "+f"(c[1]), "+f"(c[2]), "+f"(c[3])
        : "r"(a0), "r"(a1), "r"(a2), "r"(a3), "r"(b0), "r"(b1));
}
// D[16x8] += A[16x8](tf32) * B[8x8](tf32 col-major)  (pass 3)
__device__ __forceinline__ void mma8(float c[4],
                                     uint32_t a0, uint32_t a1,
                                     uint32_t a2, uint32_t a3,
                                     uint32_t b0, uint32_t b1) {
    asm("mma.sync.aligned.m16n8k8.row.col.f32.tf32.tf32.f32 "
        "{%0,%1,%2,%3}, {%4,%5,%6,%7}, {%8,%9}, {%0,%1,%2,%3};"
        : "+f"(c[0]), "+f"(c[1]), "+f"(c[2]), "+f"(c[3])
        : "r"(a0), "r"(a1), "r"(a2), "r"(a3), "r"(b0), "r"(b1));
}

// f32 fragment position (pass 3): k -> 16*(k>>4) + 4*(k&3) + ((k>>2)&3)
__device__ __forceinline__ int posk(int k) {
    return ((k >> 4) << 4) | ((k & 3) << 2) | ((k >> 2) & 3);
}

// dynamic smem (floats):
//   u32[64*80] | u16[64*80 halves] | w1h[64*80 halves] | sv0 | sv1
#define OFF_U32 0
#define OFF_U16 (NF * US)                       // 5120
#define OFF_W1H (OFF_U16 + NF * UHS / 2)        // 7680
#define OFF_SV0 (OFF_W1H + NF * UHS / 2)        // 10240
#define OFF_SV1 (OFF_SV0 + NF * SVS)            // 14592
#define DSM_FLOATS (OFF_SV1 + NF * SVS)         // 18944 -> 75776 B

__global__ void __launch_bounds__(256, 2)
afm_kernel(const float* __restrict__ x,
           const float* __restrict__ Ww,  const float* __restrict__ bw,
           const float* __restrict__ cross,
           const float* __restrict__ W1,  const float* __restrict__ b1,
           const float* __restrict__ w2,
           const float* __restrict__ Wd1, const float* __restrict__ bd1,
           const float* __restrict__ Wd2, const float* __restrict__ bd2,
           const float* __restrict__ Wd3, const float* __restrict__ bd3,
           const float* __restrict__ Wo,  const float* __restrict__ bo,
           float* __restrict__ out)
{
    extern __shared__ float dsm[];
    float*   u    = dsm + OFF_U32;
    __half*  u16p = (__half*)(dsm + OFF_U16);
    __half*  w1p  = (__half*)(dsm + OFF_W1H);
    float*   sv0  = dsm + OFF_SV0;
    float*   sv1  = dsm + OFF_SV1;

    __shared__ float xb[NF], b1s[NK], w2s[NK];
    __shared__ float redbuf[8];
    __shared__ float acc4s[4][NK];
    __shared__ float tmpv[NK];
    __shared__ float d1s[32], d2s[24], d3s[16];
    __shared__ float m_sh, denom_sh;

    const int b    = blockIdx.x;
    const int tid  = threadIdx.x;
    const int wid  = tid >> 5;
    const int lane = tid & 31;
    const int grp  = lane >> 2;     // 0..7
    const int qc   = lane & 3;      // 0..3

    if (tid < NF) {
        xb[tid]  = x[b * NF + tid];
        b1s[tid] = b1[tid];
        w2s[tid] = w2[tid];
    }
    __syncthreads();

    // stage u (fp32 fragment-major for pass3) + u16/W1 (fp16 fragment-major)
    {
        const float4* cr4 = (const float4*)cross;
        const float4* W14 = (const float4*)W1;
        __half2* u16h = (__half2*)u16p;
        __half2* w1h2 = (__half2*)w1p;
        for (int q4 = tid; q4 < NF * 16; q4 += 256) {
            const int r  = q4 >> 4;
            const int c4 = q4 & 15;
            const float s = xb[r];
            const float4 cc = cr4[q4];
            float4 uu;
            uu.x = s*cc.x; uu.y = s*cc.y; uu.z = s*cc.z; uu.w = s*cc.w;
            // u32: posk layout, row stride 80 floats
            const int kb = c4 << 2;
            const int b32 = r * US + ((kb >> 4) << 4) + ((kb >> 2) & 3);
            u[b32 + 0]  = uu.x;
            u[b32 + 4]  = uu.y;
            u[b32 + 8]  = uu.z;
            u[b32 + 12] = uu.w;
            // fp16: k=16s+8h+2q+d stored at 16s+4q+2h+d (halves), stride 80
            const int hidx = r * (UHS / 2) + 8 * (c4 >> 2) + 4 * (c4 & 1)
                             + ((c4 >> 1) & 1);
            u16h[hidx]     = __floats2half2_rn(uu.x, uu.y);
            u16h[hidx + 2] = __floats2half2_rn(uu.z, uu.w);
            const float4 w4 = W14[q4];
            w1h2[hidx]     = __floats2half2_rn(w4.x, w4.y);
            w1h2[hidx + 2] = __floats2half2_rn(w4.z, w4.w);
        }
    }
    __syncthreads();

    // ---------------- Pass 1: attention scores via fp16 mma.sync -----------
    // n-split across warp pairs: nh = wid&1 owns l in [32*nh, 32*nh+32).
    const int nh = wid & 1;
    const int wp = wid >> 1;        // 0..3

    uint2 Bc[4][4];                 // [nt][k16-step] -> (b0, b1)
    #pragma unroll
    for (int nt = 0; nt < 4; nt++) {
        const uint2* wr = (const uint2*)(w1p + ((nh * 4 + nt) * 8 + grp) * UHS);
        #pragma unroll
        for (int s = 0; s < 4; s++)
            Bc[nt][s] = wr[4 * s + qc];
    }
    // w2 fp16 B-fragments for the dot-MMA: all 8 n-columns = w2
    uint32_t w2f[2][2];
    #pragma unroll
    for (int s = 0; s < 2; s++) {
        const int base = nh * 32 + 16 * s;
        w2f[s][0] = packh2(w2s[base + 2 * qc],     w2s[base + 2 * qc + 1]);
        w2f[s][1] = packh2(w2s[base + 8 + 2 * qc], w2s[base + 8 + 2 * qc + 1]);
    }
    // bias fragments for accumulator init
    float2 b1f[4];
    #pragma unroll
    for (int nt = 0; nt < 4; nt++) {
        b1f[nt].x = b1s[nh * 32 + nt * 8 + 2 * qc];
        b1f[nt].y = b1s[nh * 32 + nt * 8 + 2 * qc + 1];
    }
    float* svp = nh ? sv1 : sv0;

    for (int p = wp; p < 72; p += 4) {
        const int t  = p >> 1;
        const int h  = p & 1;
        const int ib = TI_ARR[t] * 8 + 4 * h;   // i rows ib..ib+3
        const int jb = TJ_ARR[t] * 8;
        const uint2* uj2 = (const uint2*)(u16p + (jb + grp) * UHS);
        const uint2* ui0 = (const uint2*)(u16p + (ib + 0) * UHS);
        const uint2* ui1 = (const uint2*)(u16p + (ib + 1) * UHS);
        const uint2* ui2 = (const uint2*)(u16p + (ib + 2) * UHS);
        const uint2* ui3 = (const uint2*)(u16p + (ib + 3) * UHS);

        // init accumulators with bias (bias folded into the GEMM)
        float acc0[4][4], acc1[4][4];
        #pragma unroll
        for (int nt = 0; nt < 4; nt++) {
            acc0[nt][0] = b1f[nt].x; acc0[nt][1] = b1f[nt].y;
            acc0[nt][2] = b1f[nt].x; acc0[nt][3] = b1f[nt].y;
            acc1[nt][0] = b1f[nt].x; acc1[nt][1] = b1f[nt].y;
            acc1[nt][2] = b1f[nt].x; acc1[nt][3] = b1f[nt].y;
        }

        #pragma unroll
        for (int s = 0; s < 4; s++) {
            const int o = 4 * s + qc;
            const uint2 uj = uj2[o];
            const uint2 r0 = ui0[o];
            const uint2 r1 = ui1[o];
            const uint2 r2 = ui2[o];
            const uint2 r3 = ui3[o];
            const uint32_t a0 = hmul2(r0.x, uj.x);
            const uint32_t a1 = hmul2(r1.x, uj.x);
            const uint32_t a2 = hmul2(r0.y, uj.y);
            const uint32_t a3 = hmul2(r1.y, uj.y);
            const uint32_t c0 = hmul2(r2.x, uj.x);
            const uint32_t c1 = hmul2(r3.x, uj.x);
            const uint32_t c2 = hmul2(r2.y, uj.y);
            const uint32_t c3 = hmul2(r3.y, uj.y);
            #pragma unroll
            for (int nt = 0; nt < 4; nt++) {
                mma16(acc0[nt], a0, a1, a2, a3, Bc[nt][s].x, Bc[nt][s].y);
                mma16(acc1[nt], c0, c1, c2, c3, Bc[nt][s].x, Bc[nt][s].y);
            }
        }

        // epilogue on tensor core: s = relu(H) . w2 via m16n8k16 over k=l.
        // D1 fragments (rows=pairs, cols=l) are exactly A fragments of the
        // dot-MMA; fused relu+f16 pack; every lane ends with its rows' dots.
        float s0[4] = {0.f, 0.f, 0.f, 0.f};
        mma16(s0,
              packh2_relu(acc0[0][0], acc0[0][1]),
              packh2_relu(acc0[0][2], acc0[0][3]),
              packh2_relu(acc0[1][0], acc0[1][1]),
              packh2_relu(acc0[1][2], acc0[1][3]),
              w2f[0][0], w2f[0][1]);
        mma16(s0,
              packh2_relu(acc0[2][0], acc0[2][1]),
              packh2_relu(acc0[2][2], acc0[2][3]),
              packh2_relu(acc0[3][0], acc0[3][1]),
              packh2_relu(acc0[3][2], acc0[3][3]),
              w2f[1][0], w2f[1][1]);
        float s1[4] = {0.f, 0.f, 0.f, 0.f};
        mma16(s1,
              packh2_relu(acc1[0][0], acc1[0][1]),
              packh2_relu(acc1[0][2], acc1[0][3]),
              packh2_relu(acc1[1][0], acc1[1][1]),
              packh2_relu(acc1[1][2], acc1[1][3]),
              w2f[0][0], w2f[0][1]);
        mma16(s1,
              packh2_relu(acc1[2][0], acc1[2][1]),
              packh2_relu(acc1[2][2], acc1[2][3]),
              packh2_relu(acc1[3][0], acc1[3][1]),
              packh2_relu(acc1[3][2], acc1[3][3]),
              w2f[1][0], w2f[1][1]);

        if (qc == 0) {
            const int j = jb + grp;
            svp[(ib + 0) * SVS + j] = s0[0];   // row grp   = (ib,   j)
            svp[(ib + 1) * SVS + j] = s0[2];   // row grp+8 = (ib+1, j)
            svp[(ib + 2) * SVS + j] = s1[0];
            svp[(ib + 3) * SVS + j] = s1[2];
        }
    }
    __syncthreads();

    // ---------------- Pass 2: merge halves + masked softmax ----------------
    float sloc[16];
    float lm = -3.4e38f;
    #pragma unroll
    for (int it = 0; it < 16; it++) {
        const int lin = tid + it * 256;
        const int i = lin >> 6, j = lin & 63;
        const int sidx = i * SVS + j;
        const float s = sv0[sidx] + sv1[sidx];
        sloc[it] = s;
        const bool valid = (j >= i) && (xb[i] != 0.f) && (xb[j] != 0.f);
        if (valid) lm = fmaxf(lm, s);
    }
    #pragma unroll
    for (int d = 16; d; d >>= 1) lm = fmaxf(lm, __shfl_xor_sync(~0u, lm, d));
    if (lane == 0) redbuf[wid] = lm;
    __syncthreads();
    if (tid == 0) {
        float m = 0.f;   // max with the 0-logit seed term
        for (int w = 0; w < 8; w++) m = fmaxf(m, redbuf[w]);
        m_sh = m;
    }
    __syncthreads();
    const float m = m_sh;

    float le = 0.f;
    #pragma unroll
    for (int it = 0; it < 16; it++) {
        const int lin = tid + it * 256;
        const int i = lin >> 6, j = lin & 63;
        const bool valid = (j >= i) && (xb[i] != 0.f) && (xb[j] != 0.f);
        float e = valid ? __expf(sloc[it] - m) : 0.f;
        e = __uint_as_float(to_tf32(e));   // exactly what pass 3's MMA sees
        sv0[i * SVS + j] = e;
        le += e;
    }
    #pragma unroll
    for (int d = 16; d; d >>= 1) le += __shfl_xor_sync(~0u, le, d);
    __syncthreads();
    if (lane == 0) redbuf[wid] = le;
    __syncthreads();
    if (tid == 0) {
        float tot = __expf(-m);      // seed zeros(1) entry
        for (int w = 0; w < 8; w++) tot += redbuf[w];
        denom_sh = tot;
    }
    __syncthreads();

    // -------- Pass 3: V = E @ U via tf32 mma; tmp[k] = sum_i u[i,k] V[i,k] --
    {
        const int mt    = wid >> 1;            // 0..3
        const int nbase = (wid & 1) * 4;       // n-tiles nbase..nbase+3

        float vacc[4][4];
        #pragma unroll
        for (int cc = 0; cc < 4; cc++)
            #pragma unroll
            for (int q = 0; q < 4; q++) vacc[cc][q] = 0.f;

        int pkb[4];
        #pragma unroll
        for (int cc = 0; cc < 4; cc++)
            pkb[cc] = posk(8 * (nbase + cc) + grp);

        const float* e0 = sv0 + (16 * mt + grp) * SVS;
        const float* e1 = sv0 + (16 * mt + grp + 8) * SVS;

        #pragma unroll
        for (int js = 0; js < 8; js++) {
            const int jc = 8 * js + qc;
            const uint32_t a0 = __float_as_uint(e0[jc]);
            const uint32_t a1 = __float_as_uint(e1[jc]);
            const uint32_t a2 = __float_as_uint(e0[jc + 4]);
            const uint32_t a3 = __float_as_uint(e1[jc + 4]);
            const float* uj0 = u + jc * US;
            const float* uj1 = u + (jc + 4) * US;
            #pragma unroll
            for (int cc = 0; cc < 4; cc++) {
                const uint32_t b0 = __float_as_uint(uj0[pkb[cc]]);
                const uint32_t b1v = __float_as_uint(uj1[pkb[cc]]);
                mma8(vacc[cc], a0, a1, a2, a3, b0, b1v);
            }
        }

        float part[8];
        #pragma unroll
        for (int cc = 0; cc < 4; cc++) {
            const int k0 = 8 * (nbase + cc) + 2 * qc;
            const int i0 = 16 * mt + grp;
            const float u00 = u[i0 * US + posk(k0)];
            const float u01 = u[i0 * US + posk(k0 + 1)];
            const float u10 = u[(i0 + 8) * US + posk(k0)];
            const float u11 = u[(i0 + 8) * US + posk(k0 + 1)];
            part[2 * cc]     = fmaf(vacc[cc][0], u00, vacc[cc][2] * u10);
            part[2 * cc + 1] = fmaf(vacc[cc][1], u01, vacc[cc][3] * u11);
        }
        #pragma unroll
        for (int d = 4; d <= 16; d <<= 1)
            #pragma unroll
            for (int q = 0; q < 8; q++)
                part[q] += __shfl_xor_sync(0xffffffffu, part[q], d);

        if (grp == 0) {   // lanes 0..3 (lane == qc)
            #pragma unroll
            for (int cc = 0; cc < 4; cc++) {
                const int k0 = 8 * (nbase + cc) + 2 * qc;
                acc4s[mt][k0]     = part[2 * cc];
                acc4s[mt][k0 + 1] = part[2 * cc + 1];
            }
        }
    }
    __syncthreads();
    if (tid < NK)
        tmpv[tid] = (acc4s[0][tid] + acc4s[1][tid] +
                     acc4s[2][tid] + acc4s[3][tid]) / denom_sh;
    __syncthreads();

    // ---------------- Pass 4: deep MLP 64->32->21->16->1 + sigmoid ----------
    if (tid < 32) {
        float a = bd1[tid];
        const float* w = Wd1 + tid * 64;
        #pragma unroll 4
        for (int j = 0; j < 64; j++) a = fmaf(w[j], tmpv[j], a);
        d1s[tid] = fmaxf(a, 0.f);
    }
    __syncthreads();
    if (tid < 21) {
        float a = bd2[tid];
        const float* w = Wd2 + tid * 32;
        #pragma unroll 4
        for (int j = 0; j < 32; j++) a = fmaf(w[j], d1s[j], a);
        d2s[tid] = fmaxf(a, 0.f);
    }
    __syncthreads();
    if (tid < 16) {
        float a = bd3[tid];
        const float* w = Wd3 + tid * 21;
        for (int j = 0; j < 21; j++) a = fmaf(w[j], d2s[j], a);
        d3s[tid] = fmaxf(a, 0.f);
    }
    __syncthreads();
    if (tid == 0) {
        float o = bo[0];
        #pragma unroll
        for (int j = 0; j < 16; j++) o = fmaf(Wo[j], d3s[j], o);
        float lin = bw[0];
        #pragma unroll 4
        for (int f = 0; f < NF; f++) lin = fmaf(Ww[f], xb[f], lin);
        out[b] = 1.f / (1.f + __expf(-(lin + o)));
    }
}

extern "C" void kernel_launch(void* const* d_in, const int* in_sizes, int n_in,
                              void* d_out, int out_size)
{
    const float* x     = (const float*)d_in[0];
    const float* Ww    = (const float*)d_in[1];
    const float* bw    = (const float*)d_in[2];
    const float* cross = (const float*)d_in[3];
    const float* W1    = (const float*)d_in[4];
    const float* b1    = (const float*)d_in[5];
    const float* w2    = (const float*)d_in[6];
    const float* Wd1   = (const float*)d_in[7];
    const float* bd1   = (const float*)d_in[8];
    const float* Wd2   = (const float*)d_in[9];
    const float* bd2   = (const float*)d_in[10];
    const float* Wd3   = (const float*)d_in[11];
    const float* bd3   = (const float*)d_in[12];
    const float* Wo    = (const float*)d_in[13];
    const float* bo    = (const float*)d_in[14];
    float* out = (float*)d_out;

    const size_t dyn_smem = (size_t)DSM_FLOATS * sizeof(float); // 75,776 B
    cudaFuncSetAttribute(afm_kernel,
                         cudaFuncAttributeMaxDynamicSharedMemorySize,
                         (int)dyn_smem);

    afm_kernel<<<NB, 256, dyn_smem>>>(x, Ww, bw, cross, W1, b1, w2,
                                      Wd1, bd1, Wd2, bd2, Wd3, bd3, Wo, bo,
                                      out);
}

// round 10
// speedup vs baseline: 7.6540x; 1.1429x over previous
#include <cuda_runtime.h>
#include <cuda_fp16.h>
#include <math.h>
#include <stdint.h>

#define NB 512
#define NF 64
#define NK 64
#define US 80      // u32 row stride (floats)
#define UHS 88     // u16/w1h row stride (halves); 88 halves = 11 uint4
#define SVS 68     // sv row stride (floats)

typedef unsigned long long ull;

// upper-triangular 8x8 tile enumeration (36 tiles)
__device__ __constant__ unsigned char TI_ARR[36] = {
    0,0,0,0,0,0,0,0,
    1,1,1,1,1,1,1,
    2,2,2,2,2,2,
    3,3,3,3,3,
    4,4,4,4,
    5,5,5,
    6,6,
    7};
__device__ __constant__ unsigned char TJ_ARR[36] = {
    0,1,2,3,4,5,6,7,
    1,2,3,4,5,6,7,
    2,3,4,5,6,7,
    3,4,5,6,7,
    4,5,6,7,
    5,6,7,
    6,7,
    7};

__device__ __forceinline__ uint32_t to_tf32(float f) {
    uint32_t r;
    asm("cvt.rna.tf32.f32 %0, %1;" : "=r"(r) : "f"(f));
    return r;
}
__device__ __forceinline__ uint32_t hmul2(uint32_t a, uint32_t b) {
    uint32_t d;
    asm("mul.rn.f16x2 %0, %1, %2;" : "=r"(d) : "r"(a), "r"(b));
    return d;
}
__device__ __forceinline__ uint32_t packh2(float lo, float hi) {
    uint32_t d;
    asm("cvt.rn.f16x2.f32 %0, %1, %2;" : "=r"(d) : "f"(hi), "f"(lo));
    return d;
}
__device__ __forceinline__ uint32_t packh2_relu(float lo, float hi) {
    uint32_t d;
    asm("cvt.rn.relu.f16x2.f32 %0, %1, %2;" : "=r"(d) : "f"(hi), "f"(lo));
    return d;
}

// D[16x8] += A[16x16](f16) * B[16x8](f16 col-major), f32 accum
__device__ __forceinline__ void mma16(float c[4],
                                      uint32_t a0, uint32_t a1,
                                      uint32_t a2, uint32_t a3,
                                      uint32_t b0, uint32_t b1) {
    asm("mma.sync.aligned.m16n8k16.row.col.f32.f16.f16.f32 "
        "{%0,%1,%2,%3}, {%4,%5,%6,%7}, {%8,%9}, {%0,%1,%2,%3};"
        : "+f"(c[0]), "+f"(c[1]), "+f"(c[2]), "+f"(c[3])
        : "r"(a0), "r"(a1), "r"(a2), "r"(a3), "r"(b0), "r"(b1));
}
// D[16x8] += A[16x8](tf32) * B[8x8](tf32 col-major)  (pass 3)
__device__ __forceinline__ void mma8(float c[4],
                                     uint32_t a0, uint32_t a1,
                                     uint32_t a2, uint32_t a3,
                                     uint32_t b0, uint32_t b1) {
    asm("mma.sync.aligned.m16n8k8.row.col.f32.tf32.tf32.f32 "
        "{%0,%1,%2,%3}, {%4,%5,%6,%7}, {%8,%9}, {%0,%1,%2,%3};"
        : "+f"(c[0]), "+f"(c[1]), "+f"(c[2]), "+f"(c[3])
        : "r"(a0), "r"(a1), "r"(a2), "r"(a3), "r"(b0), "r"(b1));
}

// f32 fragment position (pass 3): k -> 16*(k>>4) + 4*(k&3) + ((k>>2)&3)
__device__ __forceinline__ int posk(int k) {
    return ((k >> 4) << 4) | ((k & 3) << 2) | ((k >> 2) & 3);
}

// dynamic smem (floats)
#define OFF_U32 0                       // 5120
#define OFF_U16 5120                    // 64*88 halves = 2816 floats
#define OFF_W1H 7936                    // 2816
#define OFF_SV0 10752                   // 4352
#define OFF_SV1 15104                   // 4352
#define OFF_WD1 19456                   // 2048
#define OFF_WD2 21504                   // 672
#define OFF_WD3 22176                   // 336
#define OFF_WO  22512                   // 16
#define OFF_WW  22528                   // 64
#define DSM_FLOATS 22592                // 90368 B

__global__ void __launch_bounds__(256, 2)
afm_kernel(const float* __restrict__ x,
           const float* __restrict__ Ww,  const float* __restrict__ bw,
           const float* __restrict__ cross,
           const float* __restrict__ W1,  const float* __restrict__ b1,
           const float* __restrict__ w2,
           const float* __restrict__ Wd1, const float* __restrict__ bd1,
           const float* __restrict__ Wd2, const float* __restrict__ bd2,
           const float* __restrict__ Wd3, const float* __restrict__ bd3,
           const float* __restrict__ Wo,  const float* __restrict__ bo,
           float* __restrict__ out)
{
    extern __shared__ float dsm[];
    float*   u    = dsm + OFF_U32;
    __half*  u16p = (__half*)(dsm + OFF_U16);
    __half*  w1p  = (__half*)(dsm + OFF_W1H);
    float*   sv0  = dsm + OFF_SV0;
    float*   sv1  = dsm + OFF_SV1;
    float*   wd1s = dsm + OFF_WD1;
    float*   wd2s = dsm + OFF_WD2;
    float*   wd3s = dsm + OFF_WD3;
    float*   wos  = dsm + OFF_WO;
    float*   wws  = dsm + OFF_WW;

    __shared__ float xb[NF], b1s[NK], w2s[NK];
    __shared__ float redbuf[16];           // [0..8) warp maxes, [8..16) warp sums
    __shared__ float acc4s[4][NK];
    __shared__ float tmpv[NK];
    __shared__ float d1s[32], d2s[24], d3s[16];

    const int b    = blockIdx.x;
    const int tid  = threadIdx.x;
    const int wid  = tid >> 5;
    const int lane = tid & 31;
    const int grp  = lane >> 2;     // 0..7
    const int qc   = lane & 3;      // 0..3

    if (tid < NF) {
        xb[tid]  = x[b * NF + tid];
        b1s[tid] = b1[tid];
        w2s[tid] = w2[tid];
    }
    __syncthreads();

    // ---- staging: u32 (posk layout), u16/W1h ((qc,s)-chunk layout),
    //      plus deep-MLP weights into smem ----
    {
        const float4* cr4 = (const float4*)cross;
        const float4* W14 = (const float4*)W1;
        __half2* u16h = (__half2*)u16p;
        __half2* w1h2 = (__half2*)w1p;
        for (int q4 = tid; q4 < NF * 16; q4 += 256) {
            const int r  = q4 >> 4;
            const int c4 = q4 & 15;
            const float s = xb[r];
            const float4 cc = cr4[q4];
            float4 uu;
            uu.x = s*cc.x; uu.y = s*cc.y; uu.z = s*cc.z; uu.w = s*cc.w;
            // u32: posk layout, row stride 80 floats
            const int kb = c4 << 2;
            const int b32 = r * US + ((kb >> 4) << 4) + ((kb >> 2) & 3);
            u[b32 + 0]  = uu.x;
            u[b32 + 4]  = uu.y;
            u[b32 + 8]  = uu.z;
            u[b32 + 12] = uu.w;
            // fp16 chunk layout: half idx = r*88 + 16*qc + 4*s + 2*e + d
            // for k = 16s + 8e + 2qc + d.  This float4 covers qc0, qc0+1.
            const int h2base = (r * UHS + (((c4 & 1) << 1) << 4)
                                + ((c4 >> 2) << 2) + (((c4 >> 1) & 1) << 1)) >> 1;
            u16h[h2base]     = __floats2half2_rn(uu.x, uu.y);
            u16h[h2base + 8] = __floats2half2_rn(uu.z, uu.w);
            const float4 w4 = W14[q4];
            w1h2[h2base]     = __floats2half2_rn(w4.x, w4.y);
            w1h2[h2base + 8] = __floats2half2_rn(w4.z, w4.w);
        }
        // deep weights -> smem (overlaps with LDG latency above)
        const float4* Wd14 = (const float4*)Wd1;
        float4* wd1s4 = (float4*)wd1s;
        for (int i = tid; i < 512; i += 256) wd1s4[i] = Wd14[i];
        if (tid < 168) ((float4*)wd2s)[tid] = ((const float4*)Wd2)[tid];
        if (tid < 84)  ((float4*)wd3s)[tid] = ((const float4*)Wd3)[tid];
        if (tid < 4)   ((float4*)wos)[tid]  = ((const float4*)Wo)[tid];
        if (tid < 16)  ((float4*)wws)[tid]  = ((const float4*)Ww)[tid];
    }
    __syncthreads();

    // ---------------- Pass 1: attention scores via fp16 mma.sync -----------
    const int nh = wid & 1;
    const int wp = wid >> 1;        // 0..3

    uint2 Bc[4][4];                 // [nt][k16-step]
    #pragma unroll
    for (int nt = 0; nt < 4; nt++) {
        const uint4* wr4 = (const uint4*)(w1p + ((nh * 4 + nt) * 8 + grp) * UHS);
        const uint4 v0 = wr4[2 * qc];
        const uint4 v1 = wr4[2 * qc + 1];
        Bc[nt][0] = make_uint2(v0.x, v0.y);
        Bc[nt][1] = make_uint2(v0.z, v0.w);
        Bc[nt][2] = make_uint2(v1.x, v1.y);
        Bc[nt][3] = make_uint2(v1.z, v1.w);
    }
    uint32_t w2f[2][2];
    #pragma unroll
    for (int s = 0; s < 2; s++) {
        const int base = nh * 32 + 16 * s;
        w2f[s][0] = packh2(w2s[base + 2 * qc],     w2s[base + 2 * qc + 1]);
        w2f[s][1] = packh2(w2s[base + 8 + 2 * qc], w2s[base + 8 + 2 * qc + 1]);
    }
    float2 b1f[4];
    #pragma unroll
    for (int nt = 0; nt < 4; nt++) {
        b1f[nt].x = b1s[nh * 32 + nt * 8 + 2 * qc];
        b1f[nt].y = b1s[nh * 32 + nt * 8 + 2 * qc + 1];
    }
    float* svp = nh ? sv1 : sv0;
    float wmax = -3.4e38f;           // max of this warp's partial scores

    for (int p = wp; p < 72; p += 4) {
        const int t  = p >> 1;
        const int h  = p & 1;
        const int ib = TI_ARR[t] * 8 + 4 * h;
        const int jb = TJ_ARR[t] * 8;
        const uint4* uj4 = (const uint4*)(u16p + (jb + grp) * UHS);
        const uint4* ua4 = (const uint4*)(u16p + ib * UHS);  // +11 per row

        float acc0[4][4], acc1[4][4];
        #pragma unroll
        for (int nt = 0; nt < 4; nt++) {
            acc0[nt][0] = b1f[nt].x; acc0[nt][1] = b1f[nt].y;
            acc0[nt][2] = b1f[nt].x; acc0[nt][3] = b1f[nt].y;
            acc1[nt][0] = b1f[nt].x; acc1[nt][1] = b1f[nt].y;
            acc1[nt][2] = b1f[nt].x; acc1[nt][3] = b1f[nt].y;
        }

        #pragma unroll
        for (int c = 0; c < 2; c++) {
            const int o = 2 * qc + c;
            const uint4 uj = uj4[o];
            const uint4 q0 = ua4[o];
            const uint4 q1 = ua4[o + 11];
            const uint4 q2 = ua4[o + 22];
            const uint4 q3 = ua4[o + 33];
            // s = 2c  uses (x, y); s = 2c+1 uses (z, w)
            {
                const uint32_t a0 = hmul2(q0.x, uj.x);
                const uint32_t a1 = hmul2(q1.x, uj.x);
                const uint32_t a2 = hmul2(q0.y, uj.y);
                const uint32_t a3 = hmul2(q1.y, uj.y);
                const uint32_t c0 = hmul2(q2.x, uj.x);
                const uint32_t c1 = hmul2(q3.x, uj.x);
                const uint32_t c2 = hmul2(q2.y, uj.y);
                const uint32_t c3 = hmul2(q3.y, uj.y);
                #pragma unroll
                for (int nt = 0; nt < 4; nt++) {
                    mma16(acc0[nt], a0, a1, a2, a3,
                          Bc[nt][2 * c].x, Bc[nt][2 * c].y);
                    mma16(acc1[nt], c0, c1, c2, c3,
                          Bc[nt][2 * c].x, Bc[nt][2 * c].y);
                }
            }
            {
                const uint32_t a0 = hmul2(q0.z, uj.z);
                const uint32_t a1 = hmul2(q1.z, uj.z);
                const uint32_t a2 = hmul2(q0.w, uj.w);
                const uint32_t a3 = hmul2(q1.w, uj.w);
                const uint32_t c0 = hmul2(q2.z, uj.z);
                const uint32_t c1 = hmul2(q3.z, uj.z);
                const uint32_t c2 = hmul2(q2.w, uj.w);
                const uint32_t c3 = hmul2(q3.w, uj.w);
                #pragma unroll
                for (int nt = 0; nt < 4; nt++) {
                    mma16(acc0[nt], a0, a1, a2, a3,
                          Bc[nt][2 * c + 1].x, Bc[nt][2 * c + 1].y);
                    mma16(acc1[nt], c0, c1, c2, c3,
                          Bc[nt][2 * c + 1].x, Bc[nt][2 * c + 1].y);
                }
            }
        }

        // tensor-core epilogue: s = relu(H) . w2 via m16n8k16 over k=l
        float s0[4] = {0.f, 0.f, 0.f, 0.f};
        mma16(s0,
              packh2_relu(acc0[0][0], acc0[0][1]),
              packh2_relu(acc0[0][2], acc0[0][3]),
              packh2_relu(acc0[1][0], acc0[1][1]),
              packh2_relu(acc0[1][2], acc0[1][3]),
              w2f[0][0], w2f[0][1]);
        mma16(s0,
              packh2_relu(acc0[2][0], acc0[2][1]),
              packh2_relu(acc0[2][2], acc0[2][3]),
              packh2_relu(acc0[3][0], acc0[3][1]),
              packh2_relu(acc0[3][2], acc0[3][3]),
              w2f[1][0], w2f[1][1]);
        float s1[4] = {0.f, 0.f, 0.f, 0.f};
        mma16(s1,
              packh2_relu(acc1[0][0], acc1[0][1]),
              packh2_relu(acc1[0][2], acc1[0][3]),
              packh2_relu(acc1[1][0], acc1[1][1]),
              packh2_relu(acc1[1][2], acc1[1][3]),
              w2f[0][0], w2f[0][1]);
        mma16(s1,
              packh2_relu(acc1[2][0], acc1[2][1]),
              packh2_relu(acc1[2][2], acc1[2][3]),
              packh2_relu(acc1[3][0], acc1[3][1]),
              packh2_relu(acc1[3][2], acc1[3][3]),
              w2f[1][0], w2f[1][1]);

        wmax = fmaxf(wmax, fmaxf(fmaxf(s0[0], s0[2]), fmaxf(s1[0], s1[2])));

        if (qc == 0) {
            const int j = jb + grp;
            svp[(ib + 0) * SVS + j] = s0[0];
            svp[(ib + 1) * SVS + j] = s0[2];
            svp[(ib + 2) * SVS + j] = s1[0];
            svp[(ib + 3) * SVS + j] = s1[2];
        }
    }
    // warp max of partial scores -> redbuf
    #pragma unroll
    for (int d = 16; d; d >>= 1)
        wmax = fmaxf(wmax, __shfl_xor_sync(~0u, wmax, d));
    if (lane == 0) redbuf[wid] = wmax;
    __syncthreads();

    // m = max(0, maxP0 + maxP1) >= true max (valid softmax shift, exact math)
    const float mP0 = fmaxf(fmaxf(redbuf[0], redbuf[2]),
                            fmaxf(redbuf[4], redbuf[6]));
    const float mP1 = fmaxf(fmaxf(redbuf[1], redbuf[3]),
                            fmaxf(redbuf[5], redbuf[7]));
    const float m = fmaxf(0.f, mP0 + mP1);

    // ---------------- Pass 2: single-loop masked softmax ----------------
    float le = 0.f;
    #pragma unroll
    for (int it = 0; it < 16; it++) {
        const int lin = tid + it * 256;
        const int i = lin >> 6, j = lin & 63;
        const int sidx = i * SVS + j;
        const bool valid = (j >= i) && (xb[i] != 0.f) && (xb[j] != 0.f);
        const float s = sv0[sidx] + sv1[sidx];
        float e = valid ? __expf(s - m) : 0.f;
        e = __uint_as_float(to_tf32(e));   // exactly what pass 3's MMA sees
        sv0[sidx] = e;
        le += e;
    }
    #pragma unroll
    for (int d = 16; d; d >>= 1) le += __shfl_xor_sync(~0u, le, d);
    if (lane == 0) redbuf[8 + wid] = le;
    __syncthreads();

    // -------- Pass 3: V = E @ U via tf32 mma; tmp[k] = sum_i u[i,k] V[i,k] --
    {
        const int mt    = wid >> 1;            // 0..3
        const int nbase = (wid & 1) * 4;       // n-tiles nbase..nbase+3

        float vacc[4][4];
        #pragma unroll
        for (int cc = 0; cc < 4; cc++)
            #pragma unroll
            for (int q = 0; q < 4; q++) vacc[cc][q] = 0.f;

        int pkb[4];
        #pragma unroll
        for (int cc = 0; cc < 4; cc++)
            pkb[cc] = posk(8 * (nbase + cc) + grp);

        const float* e0 = sv0 + (16 * mt + grp) * SVS;
        const float* e1 = sv0 + (16 * mt + grp + 8) * SVS;

        #pragma unroll
        for (int js = 0; js < 8; js++) {
            const int jc = 8 * js + qc;
            const uint32_t a0 = __float_as_uint(e0[jc]);
            const uint32_t a1 = __float_as_uint(e1[jc]);
            const uint32_t a2 = __float_as_uint(e0[jc + 4]);
            const uint32_t a3 = __float_as_uint(e1[jc + 4]);
            const float* uj0 = u + jc * US;
            const float* uj1 = u + (jc + 4) * US;
            #pragma unroll
            for (int cc = 0; cc < 4; cc++) {
                const uint32_t b0 = __float_as_uint(uj0[pkb[cc]]);
                const uint32_t b1v = __float_as_uint(uj1[pkb[cc]]);
                mma8(vacc[cc], a0, a1, a2, a3, b0, b1v);
            }
        }

        float part[8];
        #pragma unroll
        for (int cc = 0; cc < 4; cc++) {
            const int k0 = 8 * (nbase + cc) + 2 * qc;
            const int i0 = 16 * mt + grp;
            const float u00 = u[i0 * US + posk(k0)];
            const float u01 = u[i0 * US + posk(k0 + 1)];
            const float u10 = u[(i0 + 8) * US + posk(k0)];
            const float u11 = u[(i0 + 8) * US + posk(k0 + 1)];
            part[2 * cc]     = fmaf(vacc[cc][0], u00, vacc[cc][2] * u10);
            part[2 * cc + 1] = fmaf(vacc[cc][1], u01, vacc[cc][3] * u11);
        }
        #pragma unroll
        for (int d = 4; d <= 16; d <<= 1)
            #pragma unroll
            for (int q = 0; q < 8; q++)
                part[q] += __shfl_xor_sync(0xffffffffu, part[q], d);

        if (grp == 0) {
            #pragma unroll
            for (int cc = 0; cc < 4; cc++) {
                const int k0 = 8 * (nbase + cc) + 2 * qc;
                acc4s[mt][k0]     = part[2 * cc];
                acc4s[mt][k0 + 1] = part[2 * cc + 1];
            }
        }
    }
    __syncthreads();
    if (tid < NK) {
        float denom = __expf(-m);          // seed zeros(1) entry
        #pragma unroll
        for (int w = 0; w < 8; w++) denom += redbuf[8 + w];
        tmpv[tid] = (acc4s[0][tid] + acc4s[1][tid] +
                     acc4s[2][tid] + acc4s[3][tid]) / denom;
    }
    __syncthreads();

    // ---------------- Pass 4: deep MLP on warp 0 (smem weights) ------------
    if (wid == 0) {
        {
            float a = bd1[lane];
            const float4* w4 = (const float4*)(wd1s + lane * 64);
            #pragma unroll 4
            for (int j4 = 0; j4 < 16; j4++) {
                const float4 wv = w4[j4];
                a = fmaf(wv.x, tmpv[4 * j4 + 0], a);
                a = fmaf(wv.y, tmpv[4 * j4 + 1], a);
                a = fmaf(wv.z, tmpv[4 * j4 + 2], a);
                a = fmaf(wv.w, tmpv[4 * j4 + 3], a);
            }
            d1s[lane] = fmaxf(a, 0.f);
        }
        __syncwarp();
        if (lane < 21) {
            float a = bd2[lane];
            const float4* w4 = (const float4*)(wd2s + lane * 32);
            #pragma unroll
            for (int j4 = 0; j4 < 8; j4++) {
                const float4 wv = w4[j4];
                a = fmaf(wv.x, d1s[4 * j4 + 0], a);
                a = fmaf(wv.y, d1s[4 * j4 + 1], a);
                a = fmaf(wv.z, d1s[4 * j4 + 2], a);
                a = fmaf(wv.w, d1s[4 * j4 + 3], a);
            }
            d2s[lane] = fmaxf(a, 0.f);
        }
        __syncwarp();
        if (lane < 16) {
            float a = bd3[lane];
            const float* w = wd3s + lane * 21;
            #pragma unroll
            for (int j = 0; j < 21; j++) a = fmaf(w[j], d2s[j], a);
            d3s[lane] = fmaxf(a, 0.f);
        }
        __syncwarp();
        if (lane == 0) {
            float o = bo[0];
            #pragma unroll
            for (int j = 0; j < 16; j++) o = fmaf(wos[j], d3s[j], o);
            float lin = bw[0];
            #pragma unroll 8
            for (int f = 0; f < NF; f++) lin = fmaf(wws[f], xb[f], lin);
            out[b] = 1.f / (1.f + __expf(-(lin + o)));
        }
    }
}

extern "C" void kernel_launch(void* const* d_in, const int* in_sizes, int n_in,
                              void* d_out, int out_size)
{
    const float* x     = (const float*)d_in[0];
    const float* Ww    = (const float*)d_in[1];
    const float* bw    = (const float*)d_in[2];
    const float* cross = (const float*)d_in[3];
    const float* W1    = (const float*)d_in[4];
    const float* b1    = (const float*)d_in[5];
    const float* w2    = (const float*)d_in[6];
    const float* Wd1   = (const float*)d_in[7];
    const float* bd1   = (const float*)d_in[8];
    const float* Wd2   = (const float*)d_in[9];
    const float* bd2   = (const float*)d_in[10];
    const float* Wd3   = (const float*)d_in[11];
    const float* bd3   = (const float*)d_in[12];
    const float* Wo    = (const float*)d_in[13];
    const float* bo    = (const float*)d_in[14];
    float* out = (float*)d_out;

    const size_t dyn_smem = (size_t)DSM_FLOATS * sizeof(float); // 90,368 B
    cudaFuncSetAttribute(afm_kernel,
                         cudaFuncAttributeMaxDynamicSharedMemorySize,
                         (int)dyn_smem);

    afm_kernel<<<NB, 256, dyn_smem>>>(x, Ww, bw, cross, W1, b1, w2,
                                      Wd1, bd1, Wd2, bd2, Wd3, bd3, Wo, bo,
                                      out);
}